// round 13
// baseline (speedup 1.0000x reference)
#include <cuda_runtime.h>
#include <cuda_bf16.h>
#include <math.h>
#include <stdint.h>

constexpr int N = 50000;
constexpr int E = 800000;

// ---------------------------------------------------------------------------
// Device scratch (BSS zero at load; kernels restore zeros for graph replay:
//  g_deg   -> zeroed by gat2 (last reader)
//  as2/ad2 -> zeroed by gat1 (before MODE-2 GEMM accumulates)
//  out_acc/done -> reset by gat2 last block)
// ---------------------------------------------------------------------------
__device__ __align__(16) uint32_t g_xb [N * 64];   // x as bf16x2 (128 ch)
__device__ __align__(16) float g_nbr[N * 128];
__device__ __align__(16) float g_h  [N * 128];
__device__ __align__(16) uint32_t g_z1b[N * 32];   // z1 as bf16x2 (64 ch)
__device__ __align__(16) uint32_t g_z2b[N * 32];   // z2 as bf16x2
__device__ __align__(16) float g_as1[N * 8];
__device__ __align__(16) float g_ad1[N * 8];
__device__ __align__(16) float g_h2 [N * 64];
__device__ float g_as2[N];
__device__ float g_ad2[N];
__device__ float g_out_acc;
__device__ unsigned g_done;
__device__ int g_deg[N];
__device__ int g_off[N];
__device__ unsigned long long g_pack[E];
__device__ int g_csr[E];

// ---------------------------------------------------------------------------
// Helpers
// ---------------------------------------------------------------------------
__device__ __forceinline__ float lrelu(float x) { return x > 0.f ? x : 0.2f * x; }
__device__ __forceinline__ float elu1(float x)  { return x > 0.f ? x : __expf(x) - 1.f; }

__device__ __forceinline__ uint32_t pack_bf16(float a, float b) {
    __nv_bfloat162 v = __float22bfloat162_rn(make_float2(a, b));
    return *reinterpret_cast<uint32_t*>(&v);
}
__device__ __forceinline__ float2 unpack_bf16(uint32_t u) {
    return __bfloat1622float2(*reinterpret_cast<__nv_bfloat162*>(&u));
}

// m16n8k16 bf16 MMA, fp32 accumulate
__device__ __forceinline__ void mma_bf16(float c[4], const uint4& a, const uint2& b) {
    asm volatile(
        "mma.sync.aligned.m16n8k16.row.col.f32.bf16.bf16.f32 "
        "{%0,%1,%2,%3}, {%4,%5,%6,%7}, {%8,%9}, {%0,%1,%2,%3};"
        : "+f"(c[0]), "+f"(c[1]), "+f"(c[2]), "+f"(c[3])
        : "r"(a.x), "r"(a.y), "r"(a.z), "r"(a.w), "r"(b.x), "r"(b.y));
}

// ---------------------------------------------------------------------------
// hist: per-block dtype detect + histogram + packed payload (2 edges/thread)
// ---------------------------------------------------------------------------
__global__ void hist_kernel(const void* __restrict__ ei) {
    __shared__ int s_any;
    if (threadIdx.x == 0) s_any = 0;
    __syncthreads();
    const int* ei32 = (const int*)ei;
    int any = 0;
    for (int t = threadIdx.x; t < 1024; t += blockDim.x) any |= ei32[2 * t + 1];
    if (any) atomicOr(&s_any, 1);
    __syncthreads();
    const bool is64 = (s_any == 0);

    int e = (blockIdx.x * blockDim.x + threadIdx.x) * 2;
    if (e >= E) return;
    int s0, d0, s1, d1;
    if (is64) {
        const long long* p = (const long long*)ei;
        s0 = (int)p[e];     s1 = (int)p[e + 1];
        d0 = (int)p[(long long)E + e]; d1 = (int)p[(long long)E + e + 1];
    } else {
        s0 = ei32[e];     s1 = ei32[e + 1];
        d0 = ei32[E + e]; d1 = ei32[E + e + 1];
    }
    unsigned r0 = atomicAdd(&g_deg[d0], 1);
    unsigned r1 = atomicAdd(&g_deg[d1], 1);
    g_pack[e] = (unsigned long long)(unsigned)s0
              | ((unsigned long long)(unsigned)d0 << 16)
              | ((unsigned long long)r0 << 32);
    g_pack[e + 1] = (unsigned long long)(unsigned)s1
                  | ((unsigned long long)(unsigned)d1 << 16)
                  | ((unsigned long long)r1 << 32);
}

// ---------------------------------------------------------------------------
// scan: exclusive prefix of g_deg -> g_off
// ---------------------------------------------------------------------------
__global__ void scan_kernel() {
    __shared__ int wsum[32];
    __shared__ int s_carry;
    int tid = threadIdx.x, lane = tid & 31, wid = tid >> 5;
    if (tid == 0) s_carry = 0;
    __syncthreads();
    for (int base = 0; base < N; base += 1024) {
        int i = base + tid;
        int v = (i < N) ? g_deg[i] : 0;
        int s = v;
#pragma unroll
        for (int o = 1; o < 32; o <<= 1) {
            int u = __shfl_up_sync(0xffffffff, s, o);
            if (lane >= o) s += u;
        }
        if (lane == 31) wsum[wid] = s;
        __syncthreads();
        if (wid == 0) {
            int w = wsum[lane];
#pragma unroll
            for (int o = 1; o < 32; o <<= 1) {
                int u = __shfl_up_sync(0xffffffff, w, o);
                if (lane >= o) w += u;
            }
            wsum[lane] = w;
        }
        __syncthreads();
        int prev = (wid > 0) ? wsum[wid - 1] : 0;
        int carry = s_carry;
        if (i < N) g_off[i] = carry + prev + s - v;
        __syncthreads();
        if (tid == 1023) s_carry = carry + wsum[31];
        __syncthreads();
    }
}

// ---------------------------------------------------------------------------
// fill (2 edges/thread) bundled with x->bf16 convert (independent work)
// blocks [0, FILL_B): fill; blocks [FILL_B, FILL_B+CONV_B): convert
// ---------------------------------------------------------------------------
constexpr int FILL_B = (E / 2 + 255) / 256;              // 1563
constexpr int CONV_B = (N * 64 / 8 + 255) / 256;         // 1563

__global__ void fill_conv_kernel(const float* __restrict__ x) {
    if ((int)blockIdx.x < FILL_B) {
        int e = (blockIdx.x * 256 + threadIdx.x) * 2;
        if (e >= E) return;
        ulonglong2 pp = *(const ulonglong2*)&g_pack[e];
        {
            unsigned long long p = pp.x;
            g_csr[g_off[(int)((p >> 16) & 0xffffu)] + (int)(p >> 32)] = (int)(p & 0xffffu);
        }
        {
            unsigned long long p = pp.y;
            g_csr[g_off[(int)((p >> 16) & 0xffffu)] + (int)(p >> 32)] = (int)(p & 0xffffu);
        }
    } else {
        // convert: 8 bf16x2 outputs (16 floats in) per thread
        int idx = (((int)blockIdx.x - FILL_B) * 256 + threadIdx.x) * 8;
        if (idx >= N * 64) return;
        const float4* xin = (const float4*)(x + (size_t)idx * 2);
        float4 v0 = xin[0], v1 = xin[1], v2 = xin[2], v3 = xin[3];
        uint4 o0, o1;
        o0.x = pack_bf16(v0.x, v0.y); o0.y = pack_bf16(v0.z, v0.w);
        o0.z = pack_bf16(v1.x, v1.y); o0.w = pack_bf16(v1.z, v1.w);
        o1.x = pack_bf16(v2.x, v2.y); o1.y = pack_bf16(v2.z, v2.w);
        o1.z = pack_bf16(v3.x, v3.y); o1.w = pack_bf16(v3.z, v3.w);
        *(uint4*)&g_xb[idx]     = o0;
        *(uint4*)&g_xb[idx + 4] = o1;
    }
}

// ---------------------------------------------------------------------------
// GraphConv gather: quarter-warp per edge, bf16 x, fp32 accum
// ---------------------------------------------------------------------------
__global__ __launch_bounds__(256, 6) void gather_nbr_kernel() {
    int gid = blockIdx.x * blockDim.x + threadIdx.x;
    int node = gid >> 5, lane = gid & 31;
    if (node >= N) return;
    int beg = g_off[node], deg = g_deg[node];
    const int q = lane >> 3, l8 = lane & 7;

    float acc[16];
#pragma unroll
    for (int j = 0; j < 16; j++) acc[j] = 0.f;

    int k = q;
    for (; k + 4 < deg; k += 8) {
        int s0 = g_csr[beg + k], s1 = g_csr[beg + k + 4];
        uint4 a0 = *(const uint4*)&g_xb[(size_t)s0 * 64 + l8 * 8];
        uint4 b0 = *(const uint4*)&g_xb[(size_t)s0 * 64 + l8 * 8 + 4];
        uint4 a1 = *(const uint4*)&g_xb[(size_t)s1 * 64 + l8 * 8];
        uint4 b1 = *(const uint4*)&g_xb[(size_t)s1 * 64 + l8 * 8 + 4];
        const uint32_t u0[8] = {a0.x,a0.y,a0.z,a0.w,b0.x,b0.y,b0.z,b0.w};
        const uint32_t u1[8] = {a1.x,a1.y,a1.z,a1.w,b1.x,b1.y,b1.z,b1.w};
#pragma unroll
        for (int j = 0; j < 8; j++) {
            float2 p0 = unpack_bf16(u0[j]), p1 = unpack_bf16(u1[j]);
            acc[j*2]   += p0.x + p1.x;
            acc[j*2+1] += p0.y + p1.y;
        }
    }
    if (k < deg) {
        int s = g_csr[beg + k];
        uint4 a = *(const uint4*)&g_xb[(size_t)s * 64 + l8 * 8];
        uint4 b = *(const uint4*)&g_xb[(size_t)s * 64 + l8 * 8 + 4];
        const uint32_t u[8] = {a.x,a.y,a.z,a.w,b.x,b.y,b.z,b.w};
#pragma unroll
        for (int j = 0; j < 8; j++) {
            float2 p = unpack_bf16(u[j]);
            acc[j*2] += p.x; acc[j*2+1] += p.y;
        }
    }
#pragma unroll
    for (int j = 0; j < 16; j++) {
        acc[j] += __shfl_xor_sync(0xffffffff, acc[j], 8);
        acc[j] += __shfl_xor_sync(0xffffffff, acc[j], 16);
    }
    if (q == 0) {
        float* dst = g_nbr + (size_t)node * 128 + l8 * 16;
#pragma unroll
        for (int j = 0; j < 4; j++)
            *(float4*)(dst + j * 4) = make_float4(acc[j*4], acc[j*4+1], acc[j*4+2], acc[j*4+3]);
    }
}

// ---------------------------------------------------------------------------
// bf16 GEMM (m16n8k16). MODE 0: fp32 out + bias + optional ELU.
//   MODE 1: bf16 out + per-head alpha (as1/ad1).
//   MODE 2: bf16 out + single-head alpha partials via atomicAdd.
// ---------------------------------------------------------------------------
template<int BN, int MODE>
__global__ __launch_bounds__(256) void bf16_linear(
    const float* __restrict__ A1, const float* __restrict__ Wa, int K1,
    const float* __restrict__ A2, const float* __restrict__ Wb, int K2,
    const float* __restrict__ bias, void* __restrict__ Cout,
    const float* __restrict__ aS, const float* __restrict__ aD,
    int M, int NCOL, int act)
{
    constexpr int NT = BN / 16;
    __shared__ __align__(16) uint32_t As[2][8][128];
    __shared__ __align__(16) uint32_t Bs[2][BN / 8][64];
    const int tid  = threadIdx.x;
    const int lane = tid & 31, warp = tid >> 5;
    const int wm = warp & 3, wn = warp >> 2;
    const int row0 = blockIdx.x * 128, c0 = blockIdx.y * BN;

    float acc[2][NT][4];
#pragma unroll
    for (int mt = 0; mt < 2; mt++)
#pragma unroll
        for (int nt = 0; nt < NT; nt++)
#pragma unroll
            for (int j = 0; j < 4; j++) acc[mt][nt][j] = 0.f;

    const int nk1 = K1 >> 5;
    const int nk2 = A2 ? (K2 >> 5) : 0;
    for (int t = 0; t < nk1 + nk2; t++) {
        const float* A; const float* W; int K, kb;
        if (t < nk1) { A = A1; W = Wa; K = K1; kb = t << 5; }
        else         { A = A2; W = Wb; K = K2; kb = (t - nk1) << 5; }
        __syncthreads();
#pragma unroll
        for (int i = 0; i < 4; i++) {
            int idx = tid + i * 256;
            int m = idx >> 3, k4 = (idx & 7) << 2;
            float4 v = make_float4(0.f, 0.f, 0.f, 0.f);
            if (row0 + m < M) v = *(const float4*)(A + (size_t)(row0 + m) * K + kb + k4);
            uint32_t pair0 = pack_bf16(v.x, v.y);
            uint32_t pair1 = pack_bf16(v.z, v.w);
            int m16 = m >> 4, mm = m & 15, r = mm & 7, rr = mm >> 3;
            int slab = k4 >> 4, kk = k4 & 15;
            int c0l = (kk >> 1) & 3;
            int reg = rr + 2 * ((kk >> 3) & 1);
            As[slab][m16][(r * 4 + c0l) * 4 + reg]     = pair0;
            As[slab][m16][(r * 4 + c0l + 1) * 4 + reg] = pair1;
        }
#pragma unroll
        for (int i = 0; i < BN / 32; i++) {
            int idx = tid + i * 256;
            int n = idx >> 3, k4 = (idx & 7) << 2;
            float4 v = *(const float4*)(W + (size_t)(c0 + n) * K + kb + k4);
            uint32_t pair0 = pack_bf16(v.x, v.y);
            uint32_t pair1 = pack_bf16(v.z, v.w);
            int n8 = n >> 3, nn = n & 7;
            int slab = k4 >> 4, kk = k4 & 15;
            int c0l = (kk >> 1) & 3;
            int reg = (kk >> 3) & 1;
            Bs[slab][n8][(nn * 4 + c0l) * 2 + reg]     = pair0;
            Bs[slab][n8][(nn * 4 + c0l + 1) * 2 + reg] = pair1;
        }
        __syncthreads();
#pragma unroll
        for (int k16 = 0; k16 < 2; k16++) {
            uint4 a[2];
            uint2 b[NT];
            a[0] = *(const uint4*)&As[k16][wm * 2 + 0][lane * 4];
            a[1] = *(const uint4*)&As[k16][wm * 2 + 1][lane * 4];
#pragma unroll
            for (int nt = 0; nt < NT; nt++)
                b[nt] = *(const uint2*)&Bs[k16][wn * NT + nt][lane * 2];
#pragma unroll
            for (int mt = 0; mt < 2; mt++)
#pragma unroll
                for (int nt = 0; nt < NT; nt++)
                    mma_bf16(acc[mt][nt], a[mt], b[nt]);
        }
    }

    const int r = lane >> 2, cc = (lane & 3) * 2;
#pragma unroll
    for (int mt = 0; mt < 2; mt++) {
        int row  = row0 + (wm * 2 + mt) * 16 + r;
        int row2 = row + 8;
        float psl = 0.f, pdl = 0.f, psh = 0.f, pdh = 0.f;
#pragma unroll
        for (int nt = 0; nt < NT; nt++) {
            int col = c0 + (wn * NT + nt) * 8 + cc;
            float v0 = acc[mt][nt][0], v1 = acc[mt][nt][1];
            float v2 = acc[mt][nt][2], v3 = acc[mt][nt][3];
            if (MODE == 0) {
                float bx = 0.f, by = 0.f;
                if (bias) { bx = bias[col]; by = bias[col + 1]; }
                float* C = (float*)Cout;
                if (row < M) {
                    float a0 = v0 + bx, a1 = v1 + by;
                    if (act == 1) { a0 = elu1(a0); a1 = elu1(a1); }
                    *(float2*)(C + (size_t)row * NCOL + col) = make_float2(a0, a1);
                }
                if (row2 < M) {
                    float a2 = v2 + bx, a3 = v3 + by;
                    if (act == 1) { a2 = elu1(a2); a3 = elu1(a3); }
                    *(float2*)(C + (size_t)row2 * NCOL + col) = make_float2(a2, a3);
                }
            } else {
                uint32_t* Zb = (uint32_t*)Cout;
                if (row  < M) Zb[(size_t)row  * 32 + (col >> 1)] = pack_bf16(v0, v1);
                if (row2 < M) Zb[(size_t)row2 * 32 + (col >> 1)] = pack_bf16(v2, v3);
                float s0 = aS[col], s1 = aS[col + 1];
                float d0 = aD[col], d1 = aD[col + 1];
                if (MODE == 1) {
                    int h = wn * NT + nt;
                    float ps_lo = v0 * s0 + v1 * s1;
                    float pd_lo = v0 * d0 + v1 * d1;
                    float ps_hi = v2 * s0 + v3 * s1;
                    float pd_hi = v2 * d0 + v3 * d1;
                    ps_lo += __shfl_xor_sync(0xffffffff, ps_lo, 1);
                    ps_lo += __shfl_xor_sync(0xffffffff, ps_lo, 2);
                    pd_lo += __shfl_xor_sync(0xffffffff, pd_lo, 1);
                    pd_lo += __shfl_xor_sync(0xffffffff, pd_lo, 2);
                    ps_hi += __shfl_xor_sync(0xffffffff, ps_hi, 1);
                    ps_hi += __shfl_xor_sync(0xffffffff, ps_hi, 2);
                    pd_hi += __shfl_xor_sync(0xffffffff, pd_hi, 1);
                    pd_hi += __shfl_xor_sync(0xffffffff, pd_hi, 2);
                    if ((lane & 3) == 0) {
                        if (row  < M) { g_as1[(size_t)row  * 8 + h] = ps_lo; g_ad1[(size_t)row  * 8 + h] = pd_lo; }
                        if (row2 < M) { g_as1[(size_t)row2 * 8 + h] = ps_hi; g_ad1[(size_t)row2 * 8 + h] = pd_hi; }
                    }
                } else {
                    psl += v0 * s0 + v1 * s1;
                    pdl += v0 * d0 + v1 * d1;
                    psh += v2 * s0 + v3 * s1;
                    pdh += v2 * d0 + v3 * d1;
                }
            }
        }
        if (MODE == 2) {
            psl += __shfl_xor_sync(0xffffffff, psl, 1);
            psl += __shfl_xor_sync(0xffffffff, psl, 2);
            pdl += __shfl_xor_sync(0xffffffff, pdl, 1);
            pdl += __shfl_xor_sync(0xffffffff, pdl, 2);
            psh += __shfl_xor_sync(0xffffffff, psh, 1);
            psh += __shfl_xor_sync(0xffffffff, psh, 2);
            pdh += __shfl_xor_sync(0xffffffff, pdh, 1);
            pdh += __shfl_xor_sync(0xffffffff, pdh, 2);
            if ((lane & 3) == 0) {
                if (row  < M) { atomicAdd(&g_as2[row],  psl); atomicAdd(&g_ad2[row],  pdl); }
                if (row2 < M) { atomicAdd(&g_as2[row2], psh); atomicAdd(&g_ad2[row2], pdh); }
            }
        }
    }
}

// ---------------------------------------------------------------------------
// GAT1 fused: quarter-warp per edge, index-prefetch, bf16 z; zeroes as2/ad2
// ---------------------------------------------------------------------------
__global__ void gat1_fused(const float* __restrict__ b1) {
    int gid = blockIdx.x * blockDim.x + threadIdx.x;
    int node = gid >> 5, lane = gid & 31;
    if (node >= N) return;
    int beg = g_off[node], deg = g_deg[node];
    const int q = lane >> 3, l8 = lane & 7;
    const float adh = g_ad1[(size_t)node * 8 + l8];
    if (lane == 0) { g_as2[node] = 0.f; g_ad2[node] = 0.f; }

    float acc[8];
#pragma unroll
    for (int j = 0; j < 8; j++) acc[j] = 0.f;
    float den = 0.f;

    if (q == 0) {  // self-loop
        float w = __expf(lrelu(g_as1[(size_t)node * 8 + l8] + adh));
        uint4 u = *(const uint4*)&g_z1b[(size_t)node * 32 + l8 * 4];
        const uint32_t uu[4] = {u.x, u.y, u.z, u.w};
#pragma unroll
        for (int j = 0; j < 4; j++) {
            float2 p = unpack_bf16(uu[j]);
            acc[j*2] = w * p.x; acc[j*2+1] = w * p.y;
        }
        den = w;
    }
    int k = q;
    int s0 = (k < deg) ? g_csr[beg + k] : 0;
    int s1 = (k + 4 < deg) ? g_csr[beg + k + 4] : 0;
    while (k < deg) {
        int n0 = (k + 8  < deg) ? g_csr[beg + k + 8]  : 0;
        int n1 = (k + 12 < deg) ? g_csr[beg + k + 12] : 0;
        {
            float w = __expf(lrelu(g_as1[(size_t)s0 * 8 + l8] + adh));
            uint4 u = *(const uint4*)&g_z1b[(size_t)s0 * 32 + l8 * 4];
            const uint32_t uu[4] = {u.x, u.y, u.z, u.w};
#pragma unroll
            for (int j = 0; j < 4; j++) {
                float2 p = unpack_bf16(uu[j]);
                acc[j*2] += w * p.x; acc[j*2+1] += w * p.y;
            }
            den += w;
        }
        if (k + 4 < deg) {
            float w = __expf(lrelu(g_as1[(size_t)s1 * 8 + l8] + adh));
            uint4 u = *(const uint4*)&g_z1b[(size_t)s1 * 32 + l8 * 4];
            const uint32_t uu[4] = {u.x, u.y, u.z, u.w};
#pragma unroll
            for (int j = 0; j < 4; j++) {
                float2 p = unpack_bf16(uu[j]);
                acc[j*2] += w * p.x; acc[j*2+1] += w * p.y;
            }
            den += w;
        }
        s0 = n0; s1 = n1; k += 8;
    }
#pragma unroll
    for (int j = 0; j < 8; j++) {
        acc[j] += __shfl_xor_sync(0xffffffff, acc[j], 8);
        acc[j] += __shfl_xor_sync(0xffffffff, acc[j], 16);
    }
    den += __shfl_xor_sync(0xffffffff, den, 8);
    den += __shfl_xor_sync(0xffffffff, den, 16);
    if (q == 0) {
        float rh = 1.f / (den + 1e-16f);
        float* dst = g_h2 + (size_t)node * 64 + l8 * 8;
        const float* bb = b1 + l8 * 8;
#pragma unroll
        for (int j = 0; j < 2; j++) {
            float4 bv = *(const float4*)(bb + j * 4);
            *(float4*)(dst + j * 4) = make_float4(
                elu1(acc[j*4]   * rh + bv.x), elu1(acc[j*4+1] * rh + bv.y),
                elu1(acc[j*4+2] * rh + bv.z), elu1(acc[j*4+3] * rh + bv.w));
        }
    }
}

// ---------------------------------------------------------------------------
// GAT2 fused + regression head; zeroes g_deg; last block writes output
// ---------------------------------------------------------------------------
__global__ void gat2_fused(const float* __restrict__ Wr, const float* __restrict__ br,
                           const float* __restrict__ b2, float* __restrict__ out) {
    __shared__ float bp[8];
    int gid = blockIdx.x * blockDim.x + threadIdx.x;
    int node = gid >> 5, lane = gid & 31, wid = threadIdx.x >> 5;
    int beg = g_off[node], deg = g_deg[node];
    const int q = lane >> 3, l8 = lane & 7;
    const float adn = g_ad2[node];
    if (lane == 0) g_deg[node] = 0;   // restore zero for next replay

    float acc[8];
#pragma unroll
    for (int j = 0; j < 8; j++) acc[j] = 0.f;
    float den = 0.f;

    if (q == 0) {
        float w = __expf(lrelu(g_as2[node] + adn));
        uint4 u = *(const uint4*)&g_z2b[(size_t)node * 32 + l8 * 4];
        const uint32_t uu[4] = {u.x, u.y, u.z, u.w};
#pragma unroll
        for (int j = 0; j < 4; j++) {
            float2 p = unpack_bf16(uu[j]);
            acc[j*2] = w * p.x; acc[j*2+1] = w * p.y;
        }
        den = w;
    }
    int k = q;
    int s0 = (k < deg) ? g_csr[beg + k] : 0;
    int s1 = (k + 4 < deg) ? g_csr[beg + k + 4] : 0;
    while (k < deg) {
        int n0 = (k + 8  < deg) ? g_csr[beg + k + 8]  : 0;
        int n1 = (k + 12 < deg) ? g_csr[beg + k + 12] : 0;
        {
            float w = __expf(lrelu(g_as2[s0] + adn));
            uint4 u = *(const uint4*)&g_z2b[(size_t)s0 * 32 + l8 * 4];
            const uint32_t uu[4] = {u.x, u.y, u.z, u.w};
#pragma unroll
            for (int j = 0; j < 4; j++) {
                float2 p = unpack_bf16(uu[j]);
                acc[j*2] += w * p.x; acc[j*2+1] += w * p.y;
            }
            den += w;
        }
        if (k + 4 < deg) {
            float w = __expf(lrelu(g_as2[s1] + adn));
            uint4 u = *(const uint4*)&g_z2b[(size_t)s1 * 32 + l8 * 4];
            const uint32_t uu[4] = {u.x, u.y, u.z, u.w};
#pragma unroll
            for (int j = 0; j < 4; j++) {
                float2 p = unpack_bf16(uu[j]);
                acc[j*2] += w * p.x; acc[j*2+1] += w * p.y;
            }
            den += w;
        }
        s0 = n0; s1 = n1; k += 8;
    }
#pragma unroll
    for (int j = 0; j < 8; j++) {
        acc[j] += __shfl_xor_sync(0xffffffff, acc[j], 8);
        acc[j] += __shfl_xor_sync(0xffffffff, acc[j], 16);
    }
    den += __shfl_xor_sync(0xffffffff, den, 8);
    den += __shfl_xor_sync(0xffffffff, den, 16);

    float pd = 0.f;
    const float* wp = Wr + l8 * 8;
#pragma unroll
    for (int j = 0; j < 8; j++) pd += acc[j] * wp[j];
    pd += __shfl_xor_sync(0xffffffff, pd, 1);
    pd += __shfl_xor_sync(0xffffffff, pd, 2);
    pd += __shfl_xor_sync(0xffffffff, pd, 4);
    if (lane == 0) bp[wid] = pd / (den + 1e-16f);
    __syncthreads();
    if (threadIdx.x == 0) {
        float s = 0.f;
#pragma unroll
        for (int j = 0; j < 8; j++) s += bp[j];
        atomicAdd(&g_out_acc, s);
        __threadfence();
        unsigned old = atomicAdd(&g_done, 1u);
        if (old == gridDim.x - 1) {
            float total = atomicExch(&g_out_acc, 0.f);
            float bwr = 0.f;
            for (int i = 0; i < 64; i++) bwr += b2[i] * Wr[i];
            out[0] = total * (1.0f / (float)N) + bwr + br[0];
            g_done = 0;
        }
    }
}

// ---------------------------------------------------------------------------
// Launch (8 kernels)
// ---------------------------------------------------------------------------
extern "C" void kernel_launch(void* const* d_in, const int* in_sizes, int n_in,
                              void* d_out, int out_size) {
    const float* x      = (const float*)d_in[0];
    const void*  ei     = d_in[1];
    const float* W_rel  = (const float*)d_in[2];
    const float* b_rel  = (const float*)d_in[3];
    const float* W_root = (const float*)d_in[4];
    const float* W1     = (const float*)d_in[5];
    const float* a1s    = (const float*)d_in[6];
    const float* a1d    = (const float*)d_in[7];
    const float* b1     = (const float*)d_in[8];
    const float* W2     = (const float*)d_in[9];
    const float* a2s    = (const float*)d_in[10];
    const float* a2d    = (const float*)d_in[11];
    const float* b2     = (const float*)d_in[12];
    const float* Wr     = (const float*)d_in[13];
    const float* br     = (const float*)d_in[14];
    float* out          = (float*)d_out;

    float *p_nbr, *p_h, *p_h2;
    void *p_z1b, *p_z2b;
    cudaGetSymbolAddress((void**)&p_nbr, g_nbr);
    cudaGetSymbolAddress((void**)&p_h,   g_h);
    cudaGetSymbolAddress(&p_z1b, g_z1b);
    cudaGetSymbolAddress((void**)&p_h2,  g_h2);
    cudaGetSymbolAddress(&p_z2b, g_z2b);

    hist_kernel<<<(E / 2 + 255) / 256, 256>>>(ei);
    scan_kernel<<<1, 1024>>>();
    fill_conv_kernel<<<FILL_B + CONV_B, 256>>>(x);

    gather_nbr_kernel<<<(N * 32 + 255) / 256, 256>>>();
    {
        dim3 g((N + 127) / 128, 1);
        bf16_linear<128, 0><<<g, 256>>>(p_nbr, W_rel, 128, x, W_root, 128,
                                        b_rel, p_h, nullptr, nullptr, N, 128, 1);
    }
    {
        dim3 g((N + 127) / 128, 1);
        bf16_linear<64, 1><<<g, 256>>>(p_h, W1, 128, nullptr, nullptr, 0,
                                       nullptr, p_z1b, a1s, a1d, N, 64, 0);
    }
    gat1_fused<<<(N * 32 + 255) / 256, 256>>>(b1);

    {
        dim3 g((N + 127) / 128, 1);
        bf16_linear<64, 2><<<g, 256>>>(p_h2, W2, 64, nullptr, nullptr, 0,
                                       nullptr, p_z2b, a2s, a2d, N, 64, 0);
    }
    gat2_fused<<<N * 32 / 256, 256>>>(Wr, br, b2, out);
}

// round 14
// speedup vs baseline: 1.1522x; 1.1522x over previous
#include <cuda_runtime.h>
#include <cuda_bf16.h>
#include <math.h>
#include <stdint.h>

constexpr int N = 50000;
constexpr int E = 800000;

// ---------------------------------------------------------------------------
// Device scratch
// ---------------------------------------------------------------------------
__device__ __align__(16) uint32_t g_xb [N * 64];   // x as bf16x2 (128 ch)
__device__ __align__(16) float g_nbr[N * 128];
__device__ __align__(16) float g_h  [N * 128];
__device__ __align__(16) uint32_t g_z1b[N * 32];   // z1 as bf16x2 (64 ch)
__device__ __align__(16) uint32_t g_z2b[N * 32];   // z2 as bf16x2
__device__ __align__(16) float g_as1[N * 8];
__device__ __align__(16) float g_ad1[N * 8];
__device__ __align__(16) float g_h2 [N * 64];
__device__ float g_as2[N];
__device__ float g_ad2[N];
__device__ float g_out_acc;          // reset by gat2 last block
__device__ unsigned g_done;          // reset by gat2 last block
__device__ int g_deg[N];
__device__ int g_off[N];
__device__ unsigned long long g_pack[E];
__device__ int g_csr[E];
__device__ int g_is64;

// ---------------------------------------------------------------------------
// Helpers
// ---------------------------------------------------------------------------
__device__ __forceinline__ float lrelu(float x) { return x > 0.f ? x : 0.2f * x; }
__device__ __forceinline__ float elu1(float x)  { return x > 0.f ? x : __expf(x) - 1.f; }

__device__ __forceinline__ uint32_t pack_bf16(float a, float b) {
    __nv_bfloat162 v = __float22bfloat162_rn(make_float2(a, b));
    return *reinterpret_cast<uint32_t*>(&v);
}
__device__ __forceinline__ float2 unpack_bf16(uint32_t u) {
    return __bfloat1622float2(*reinterpret_cast<__nv_bfloat162*>(&u));
}

// m16n8k16 bf16 MMA, fp32 accumulate
__device__ __forceinline__ void mma_bf16(float c[4], const uint4& a, const uint2& b) {
    asm volatile(
        "mma.sync.aligned.m16n8k16.row.col.f32.bf16.bf16.f32 "
        "{%0,%1,%2,%3}, {%4,%5,%6,%7}, {%8,%9}, {%0,%1,%2,%3};"
        : "+f"(c[0]), "+f"(c[1]), "+f"(c[2]), "+f"(c[3])
        : "r"(a.x), "r"(a.y), "r"(a.z), "r"(a.w), "r"(b.x), "r"(b.y));
}

__device__ __forceinline__ int edge_id(const void* ei, long long idx) {
    return g_is64 ? (int)((const long long*)ei)[idx] : ((const int*)ei)[idx];
}
__device__ __forceinline__ int edge_src(const void* ei, int e) { return edge_id(ei, e); }
__device__ __forceinline__ int edge_dst(const void* ei, int e) { return edge_id(ei, (long long)E + e); }

// ---------------------------------------------------------------------------
// init: zero counters + dtype detect (block 0).  (x convert moved to scan)
// ---------------------------------------------------------------------------
__global__ void init_kernel(const int* ei) {
    int i = blockIdx.x * blockDim.x + threadIdx.x;
    int stride = gridDim.x * blockDim.x;
    for (int t = i; t < N; t += stride) { g_deg[t] = 0; g_as2[t] = 0.f; g_ad2[t] = 0.f; }
    if (blockIdx.x == 0) {
        __shared__ int any;
        if (threadIdx.x == 0) any = 0;
        __syncthreads();
        for (int t = threadIdx.x; t < 1024; t += blockDim.x)
            if (ei[2 * t + 1] != 0) atomicOr(&any, 1);
        __syncthreads();
        if (threadIdx.x == 0) g_is64 = any ? 0 : 1;
    }
}

// ---------------------------------------------------------------------------
// CSR build: hist captures rank + packs (src|dst|rank)
// ---------------------------------------------------------------------------
__global__ void hist_kernel(const void* __restrict__ ei) {
    int e = blockIdx.x * blockDim.x + threadIdx.x;
    if (e >= E) return;
    int s = edge_src(ei, e), d = edge_dst(ei, e);
    unsigned rank = atomicAdd(&g_deg[d], 1);
    g_pack[e] = (unsigned long long)(unsigned)s
              | ((unsigned long long)(unsigned)d << 16)
              | ((unsigned long long)rank << 32);
}

// ---------------------------------------------------------------------------
// scan (block 0) + x->bf16 convert (blocks >= 1, riding in the scan's shadow)
// ---------------------------------------------------------------------------
constexpr int CONV_B = (N * 64 / 8 + 1023) / 1024;   // 391 blocks of 1024 thr

__global__ void scan_conv_kernel(const float* __restrict__ x) {
    if (blockIdx.x > 0) {
        // convert: 8 bf16x2 outputs (16 floats in) per thread
        int idx = (((int)blockIdx.x - 1) * 1024 + threadIdx.x) * 8;
        if (idx >= N * 64) return;
        const float4* xin = (const float4*)(x + (size_t)idx * 2);
        float4 v0 = xin[0], v1 = xin[1], v2 = xin[2], v3 = xin[3];
        uint4 o0, o1;
        o0.x = pack_bf16(v0.x, v0.y); o0.y = pack_bf16(v0.z, v0.w);
        o0.z = pack_bf16(v1.x, v1.y); o0.w = pack_bf16(v1.z, v1.w);
        o1.x = pack_bf16(v2.x, v2.y); o1.y = pack_bf16(v2.z, v2.w);
        o1.z = pack_bf16(v3.x, v3.y); o1.w = pack_bf16(v3.z, v3.w);
        *(uint4*)&g_xb[idx]     = o0;
        *(uint4*)&g_xb[idx + 4] = o1;
        return;
    }
    __shared__ int wsum[32];
    __shared__ int s_carry;
    int tid = threadIdx.x, lane = tid & 31, wid = tid >> 5;
    if (tid == 0) s_carry = 0;
    __syncthreads();
    for (int base = 0; base < N; base += 1024) {
        int i = base + tid;
        int v = (i < N) ? g_deg[i] : 0;
        int s = v;
#pragma unroll
        for (int o = 1; o < 32; o <<= 1) {
            int u = __shfl_up_sync(0xffffffff, s, o);
            if (lane >= o) s += u;
        }
        if (lane == 31) wsum[wid] = s;
        __syncthreads();
        if (wid == 0) {
            int w = wsum[lane];
#pragma unroll
            for (int o = 1; o < 32; o <<= 1) {
                int u = __shfl_up_sync(0xffffffff, w, o);
                if (lane >= o) w += u;
            }
            wsum[lane] = w;
        }
        __syncthreads();
        int prev = (wid > 0) ? wsum[wid - 1] : 0;
        int carry = s_carry;
        if (i < N) g_off[i] = carry + prev + s - v;
        __syncthreads();
        if (tid == 1023) s_carry = carry + wsum[31];
        __syncthreads();
    }
}

// fill: 2 edges per thread, one 16B pack load
__global__ void fill_kernel() {
    int e = (blockIdx.x * blockDim.x + threadIdx.x) * 2;
    if (e >= E) return;
    ulonglong2 pp = *(const ulonglong2*)&g_pack[e];
    {
        unsigned long long p = pp.x;
        g_csr[g_off[(int)((p >> 16) & 0xffffu)] + (int)(p >> 32)] = (int)(p & 0xffffu);
    }
    {
        unsigned long long p = pp.y;
        g_csr[g_off[(int)((p >> 16) & 0xffffu)] + (int)(p >> 32)] = (int)(p & 0xffffu);
    }
}

// ---------------------------------------------------------------------------
// GraphConv gather: quarter-warp per edge, bf16 x, fp32 accum
// ---------------------------------------------------------------------------
__global__ __launch_bounds__(256, 6) void gather_nbr_kernel() {
    int gid = blockIdx.x * blockDim.x + threadIdx.x;
    int node = gid >> 5, lane = gid & 31;
    if (node >= N) return;
    int beg = g_off[node], deg = g_deg[node];
    const int q = lane >> 3, l8 = lane & 7;

    float acc[16];
#pragma unroll
    for (int j = 0; j < 16; j++) acc[j] = 0.f;

    int k = q;
    for (; k + 4 < deg; k += 8) {
        int s0 = g_csr[beg + k], s1 = g_csr[beg + k + 4];
        uint4 a0 = *(const uint4*)&g_xb[(size_t)s0 * 64 + l8 * 8];
        uint4 b0 = *(const uint4*)&g_xb[(size_t)s0 * 64 + l8 * 8 + 4];
        uint4 a1 = *(const uint4*)&g_xb[(size_t)s1 * 64 + l8 * 8];
        uint4 b1 = *(const uint4*)&g_xb[(size_t)s1 * 64 + l8 * 8 + 4];
        const uint32_t u0[8] = {a0.x,a0.y,a0.z,a0.w,b0.x,b0.y,b0.z,b0.w};
        const uint32_t u1[8] = {a1.x,a1.y,a1.z,a1.w,b1.x,b1.y,b1.z,b1.w};
#pragma unroll
        for (int j = 0; j < 8; j++) {
            float2 p0 = unpack_bf16(u0[j]), p1 = unpack_bf16(u1[j]);
            acc[j*2]   += p0.x + p1.x;
            acc[j*2+1] += p0.y + p1.y;
        }
    }
    if (k < deg) {
        int s = g_csr[beg + k];
        uint4 a = *(const uint4*)&g_xb[(size_t)s * 64 + l8 * 8];
        uint4 b = *(const uint4*)&g_xb[(size_t)s * 64 + l8 * 8 + 4];
        const uint32_t u[8] = {a.x,a.y,a.z,a.w,b.x,b.y,b.z,b.w};
#pragma unroll
        for (int j = 0; j < 8; j++) {
            float2 p = unpack_bf16(u[j]);
            acc[j*2] += p.x; acc[j*2+1] += p.y;
        }
    }
#pragma unroll
    for (int j = 0; j < 16; j++) {
        acc[j] += __shfl_xor_sync(0xffffffff, acc[j], 8);
        acc[j] += __shfl_xor_sync(0xffffffff, acc[j], 16);
    }
    if (q == 0) {
        float* dst = g_nbr + (size_t)node * 128 + l8 * 16;
#pragma unroll
        for (int j = 0; j < 4; j++)
            *(float4*)(dst + j * 4) = make_float4(acc[j*4], acc[j*4+1], acc[j*4+2], acc[j*4+3]);
    }
}

// ---------------------------------------------------------------------------
// bf16 GEMM (m16n8k16). MODE 0: fp32 out + bias + optional ELU.
//   MODE 1: bf16 out + per-head alpha (as1/ad1).
//   MODE 2: bf16 out + single-head alpha partials via atomicAdd.
// ---------------------------------------------------------------------------
template<int BN, int MODE>
__global__ __launch_bounds__(256) void bf16_linear(
    const float* __restrict__ A1, const float* __restrict__ Wa, int K1,
    const float* __restrict__ A2, const float* __restrict__ Wb, int K2,
    const float* __restrict__ bias, void* __restrict__ Cout,
    const float* __restrict__ aS, const float* __restrict__ aD,
    int M, int NCOL, int act)
{
    constexpr int NT = BN / 16;
    __shared__ __align__(16) uint32_t As[2][8][128];
    __shared__ __align__(16) uint32_t Bs[2][BN / 8][64];
    const int tid  = threadIdx.x;
    const int lane = tid & 31, warp = tid >> 5;
    const int wm = warp & 3, wn = warp >> 2;
    const int row0 = blockIdx.x * 128, c0 = blockIdx.y * BN;

    float acc[2][NT][4];
#pragma unroll
    for (int mt = 0; mt < 2; mt++)
#pragma unroll
        for (int nt = 0; nt < NT; nt++)
#pragma unroll
            for (int j = 0; j < 4; j++) acc[mt][nt][j] = 0.f;

    const int nk1 = K1 >> 5;
    const int nk2 = A2 ? (K2 >> 5) : 0;
    for (int t = 0; t < nk1 + nk2; t++) {
        const float* A; const float* W; int K, kb;
        if (t < nk1) { A = A1; W = Wa; K = K1; kb = t << 5; }
        else         { A = A2; W = Wb; K = K2; kb = (t - nk1) << 5; }
        __syncthreads();
#pragma unroll
        for (int i = 0; i < 4; i++) {
            int idx = tid + i * 256;
            int m = idx >> 3, k4 = (idx & 7) << 2;
            float4 v = make_float4(0.f, 0.f, 0.f, 0.f);
            if (row0 + m < M) v = *(const float4*)(A + (size_t)(row0 + m) * K + kb + k4);
            uint32_t pair0 = pack_bf16(v.x, v.y);
            uint32_t pair1 = pack_bf16(v.z, v.w);
            int m16 = m >> 4, mm = m & 15, r = mm & 7, rr = mm >> 3;
            int slab = k4 >> 4, kk = k4 & 15;
            int c0l = (kk >> 1) & 3;
            int reg = rr + 2 * ((kk >> 3) & 1);
            As[slab][m16][(r * 4 + c0l) * 4 + reg]     = pair0;
            As[slab][m16][(r * 4 + c0l + 1) * 4 + reg] = pair1;
        }
#pragma unroll
        for (int i = 0; i < BN / 32; i++) {
            int idx = tid + i * 256;
            int n = idx >> 3, k4 = (idx & 7) << 2;
            float4 v = *(const float4*)(W + (size_t)(c0 + n) * K + kb + k4);
            uint32_t pair0 = pack_bf16(v.x, v.y);
            uint32_t pair1 = pack_bf16(v.z, v.w);
            int n8 = n >> 3, nn = n & 7;
            int slab = k4 >> 4, kk = k4 & 15;
            int c0l = (kk >> 1) & 3;
            int reg = (kk >> 3) & 1;
            Bs[slab][n8][(nn * 4 + c0l) * 2 + reg]     = pair0;
            Bs[slab][n8][(nn * 4 + c0l + 1) * 2 + reg] = pair1;
        }
        __syncthreads();
#pragma unroll
        for (int k16 = 0; k16 < 2; k16++) {
            uint4 a[2];
            uint2 b[NT];
            a[0] = *(const uint4*)&As[k16][wm * 2 + 0][lane * 4];
            a[1] = *(const uint4*)&As[k16][wm * 2 + 1][lane * 4];
#pragma unroll
            for (int nt = 0; nt < NT; nt++)
                b[nt] = *(const uint2*)&Bs[k16][wn * NT + nt][lane * 2];
#pragma unroll
            for (int mt = 0; mt < 2; mt++)
#pragma unroll
                for (int nt = 0; nt < NT; nt++)
                    mma_bf16(acc[mt][nt], a[mt], b[nt]);
        }
    }

    const int r = lane >> 2, cc = (lane & 3) * 2;
#pragma unroll
    for (int mt = 0; mt < 2; mt++) {
        int row  = row0 + (wm * 2 + mt) * 16 + r;
        int row2 = row + 8;
        float psl = 0.f, pdl = 0.f, psh = 0.f, pdh = 0.f;
#pragma unroll
        for (int nt = 0; nt < NT; nt++) {
            int col = c0 + (wn * NT + nt) * 8 + cc;
            float v0 = acc[mt][nt][0], v1 = acc[mt][nt][1];
            float v2 = acc[mt][nt][2], v3 = acc[mt][nt][3];
            if (MODE == 0) {
                float bx = 0.f, by = 0.f;
                if (bias) { bx = bias[col]; by = bias[col + 1]; }
                float* C = (float*)Cout;
                if (row < M) {
                    float a0 = v0 + bx, a1 = v1 + by;
                    if (act == 1) { a0 = elu1(a0); a1 = elu1(a1); }
                    *(float2*)(C + (size_t)row * NCOL + col) = make_float2(a0, a1);
                }
                if (row2 < M) {
                    float a2 = v2 + bx, a3 = v3 + by;
                    if (act == 1) { a2 = elu1(a2); a3 = elu1(a3); }
                    *(float2*)(C + (size_t)row2 * NCOL + col) = make_float2(a2, a3);
                }
            } else {
                uint32_t* Zb = (uint32_t*)Cout;
                if (row  < M) Zb[(size_t)row  * 32 + (col >> 1)] = pack_bf16(v0, v1);
                if (row2 < M) Zb[(size_t)row2 * 32 + (col >> 1)] = pack_bf16(v2, v3);
                float s0 = aS[col], s1 = aS[col + 1];
                float d0 = aD[col], d1 = aD[col + 1];
                if (MODE == 1) {
                    int h = wn * NT + nt;
                    float ps_lo = v0 * s0 + v1 * s1;
                    float pd_lo = v0 * d0 + v1 * d1;
                    float ps_hi = v2 * s0 + v3 * s1;
                    float pd_hi = v2 * d0 + v3 * d1;
                    ps_lo += __shfl_xor_sync(0xffffffff, ps_lo, 1);
                    ps_lo += __shfl_xor_sync(0xffffffff, ps_lo, 2);
                    pd_lo += __shfl_xor_sync(0xffffffff, pd_lo, 1);
                    pd_lo += __shfl_xor_sync(0xffffffff, pd_lo, 2);
                    ps_hi += __shfl_xor_sync(0xffffffff, ps_hi, 1);
                    ps_hi += __shfl_xor_sync(0xffffffff, ps_hi, 2);
                    pd_hi += __shfl_xor_sync(0xffffffff, pd_hi, 1);
                    pd_hi += __shfl_xor_sync(0xffffffff, pd_hi, 2);
                    if ((lane & 3) == 0) {
                        if (row  < M) { g_as1[(size_t)row  * 8 + h] = ps_lo; g_ad1[(size_t)row  * 8 + h] = pd_lo; }
                        if (row2 < M) { g_as1[(size_t)row2 * 8 + h] = ps_hi; g_ad1[(size_t)row2 * 8 + h] = pd_hi; }
                    }
                } else {
                    psl += v0 * s0 + v1 * s1;
                    pdl += v0 * d0 + v1 * d1;
                    psh += v2 * s0 + v3 * s1;
                    pdh += v2 * d0 + v3 * d1;
                }
            }
        }
        if (MODE == 2) {
            psl += __shfl_xor_sync(0xffffffff, psl, 1);
            psl += __shfl_xor_sync(0xffffffff, psl, 2);
            pdl += __shfl_xor_sync(0xffffffff, pdl, 1);
            pdl += __shfl_xor_sync(0xffffffff, pdl, 2);
            psh += __shfl_xor_sync(0xffffffff, psh, 1);
            psh += __shfl_xor_sync(0xffffffff, psh, 2);
            pdh += __shfl_xor_sync(0xffffffff, pdh, 1);
            pdh += __shfl_xor_sync(0xffffffff, pdh, 2);
            if ((lane & 3) == 0) {
                if (row  < M) { atomicAdd(&g_as2[row],  psl); atomicAdd(&g_ad2[row],  pdl); }
                if (row2 < M) { atomicAdd(&g_as2[row2], psh); atomicAdd(&g_ad2[row2], pdh); }
            }
        }
    }
}

// ---------------------------------------------------------------------------
// GAT1 fused: quarter-warp per edge (2 edges in flight), bf16 z
// ---------------------------------------------------------------------------
__global__ void gat1_fused(const float* __restrict__ b1) {
    int gid = blockIdx.x * blockDim.x + threadIdx.x;
    int node = gid >> 5, lane = gid & 31;
    if (node >= N) return;
    int beg = g_off[node], deg = g_deg[node];
    const int q = lane >> 3, l8 = lane & 7;
    const float adh = g_ad1[(size_t)node * 8 + l8];

    float acc[8];
#pragma unroll
    for (int j = 0; j < 8; j++) acc[j] = 0.f;
    float den = 0.f;

    if (q == 0) {  // self-loop
        float w = __expf(lrelu(g_as1[(size_t)node * 8 + l8] + adh));
        uint4 u = *(const uint4*)&g_z1b[(size_t)node * 32 + l8 * 4];
        const uint32_t uu[4] = {u.x, u.y, u.z, u.w};
#pragma unroll
        for (int j = 0; j < 4; j++) {
            float2 p = unpack_bf16(uu[j]);
            acc[j*2] = w * p.x; acc[j*2+1] = w * p.y;
        }
        den = w;
    }
    int k = q;
    for (; k + 4 < deg; k += 8) {
        int s0 = g_csr[beg + k], s1 = g_csr[beg + k + 4];
        float w0 = __expf(lrelu(g_as1[(size_t)s0 * 8 + l8] + adh));
        float w1 = __expf(lrelu(g_as1[(size_t)s1 * 8 + l8] + adh));
        uint4 u0 = *(const uint4*)&g_z1b[(size_t)s0 * 32 + l8 * 4];
        uint4 u1 = *(const uint4*)&g_z1b[(size_t)s1 * 32 + l8 * 4];
        const uint32_t a0[4] = {u0.x, u0.y, u0.z, u0.w};
        const uint32_t a1[4] = {u1.x, u1.y, u1.z, u1.w};
#pragma unroll
        for (int j = 0; j < 4; j++) {
            float2 p0 = unpack_bf16(a0[j]), p1 = unpack_bf16(a1[j]);
            acc[j*2]   += w0 * p0.x + w1 * p1.x;
            acc[j*2+1] += w0 * p0.y + w1 * p1.y;
        }
        den += w0 + w1;
    }
    if (k < deg) {
        int s = g_csr[beg + k];
        float w = __expf(lrelu(g_as1[(size_t)s * 8 + l8] + adh));
        uint4 u = *(const uint4*)&g_z1b[(size_t)s * 32 + l8 * 4];
        const uint32_t uu[4] = {u.x, u.y, u.z, u.w};
#pragma unroll
        for (int j = 0; j < 4; j++) {
            float2 p = unpack_bf16(uu[j]);
            acc[j*2] += w * p.x; acc[j*2+1] += w * p.y;
        }
        den += w;
    }
#pragma unroll
    for (int j = 0; j < 8; j++) {
        acc[j] += __shfl_xor_sync(0xffffffff, acc[j], 8);
        acc[j] += __shfl_xor_sync(0xffffffff, acc[j], 16);
    }
    den += __shfl_xor_sync(0xffffffff, den, 8);
    den += __shfl_xor_sync(0xffffffff, den, 16);
    if (q == 0) {
        float rh = 1.f / (den + 1e-16f);
        float* dst = g_h2 + (size_t)node * 64 + l8 * 8;
        const float* bb = b1 + l8 * 8;
#pragma unroll
        for (int j = 0; j < 2; j++) {
            float4 bv = *(const float4*)(bb + j * 4);
            *(float4*)(dst + j * 4) = make_float4(
                elu1(acc[j*4]   * rh + bv.x), elu1(acc[j*4+1] * rh + bv.y),
                elu1(acc[j*4+2] * rh + bv.z), elu1(acc[j*4+3] * rh + bv.w));
        }
    }
}

// ---------------------------------------------------------------------------
// GAT2 fused + regression head; last block writes the final output
// ---------------------------------------------------------------------------
__global__ void gat2_fused(const float* __restrict__ Wr, const float* __restrict__ br,
                           const float* __restrict__ b2, float* __restrict__ out) {
    __shared__ float bp[8];
    int gid = blockIdx.x * blockDim.x + threadIdx.x;
    int node = gid >> 5, lane = gid & 31, wid = threadIdx.x >> 5;
    int beg = g_off[node], deg = g_deg[node];
    const int q = lane >> 3, l8 = lane & 7;
    const float adn = g_ad2[node];

    float acc[8];
#pragma unroll
    for (int j = 0; j < 8; j++) acc[j] = 0.f;
    float den = 0.f;

    if (q == 0) {
        float w = __expf(lrelu(g_as2[node] + adn));
        uint4 u = *(const uint4*)&g_z2b[(size_t)node * 32 + l8 * 4];
        const uint32_t uu[4] = {u.x, u.y, u.z, u.w};
#pragma unroll
        for (int j = 0; j < 4; j++) {
            float2 p = unpack_bf16(uu[j]);
            acc[j*2] = w * p.x; acc[j*2+1] = w * p.y;
        }
        den = w;
    }
    int k = q;
    for (; k + 4 < deg; k += 8) {
        int s0 = g_csr[beg + k], s1 = g_csr[beg + k + 4];
        float w0 = __expf(lrelu(g_as2[s0] + adn));
        float w1 = __expf(lrelu(g_as2[s1] + adn));
        uint4 u0 = *(const uint4*)&g_z2b[(size_t)s0 * 32 + l8 * 4];
        uint4 u1 = *(const uint4*)&g_z2b[(size_t)s1 * 32 + l8 * 4];
        const uint32_t a0[4] = {u0.x, u0.y, u0.z, u0.w};
        const uint32_t a1[4] = {u1.x, u1.y, u1.z, u1.w};
#pragma unroll
        for (int j = 0; j < 4; j++) {
            float2 p0 = unpack_bf16(a0[j]), p1 = unpack_bf16(a1[j]);
            acc[j*2]   += w0 * p0.x + w1 * p1.x;
            acc[j*2+1] += w0 * p0.y + w1 * p1.y;
        }
        den += w0 + w1;
    }
    if (k < deg) {
        int s = g_csr[beg + k];
        float w = __expf(lrelu(g_as2[s] + adn));
        uint4 u = *(const uint4*)&g_z2b[(size_t)s * 32 + l8 * 4];
        const uint32_t uu[4] = {u.x, u.y, u.z, u.w};
#pragma unroll
        for (int j = 0; j < 4; j++) {
            float2 p = unpack_bf16(uu[j]);
            acc[j*2] += w * p.x; acc[j*2+1] += w * p.y;
        }
        den += w;
    }
#pragma unroll
    for (int j = 0; j < 8; j++) {
        acc[j] += __shfl_xor_sync(0xffffffff, acc[j], 8);
        acc[j] += __shfl_xor_sync(0xffffffff, acc[j], 16);
    }
    den += __shfl_xor_sync(0xffffffff, den, 8);
    den += __shfl_xor_sync(0xffffffff, den, 16);

    float pd = 0.f;
    const float* wp = Wr + l8 * 8;
#pragma unroll
    for (int j = 0; j < 8; j++) pd += acc[j] * wp[j];
    pd += __shfl_xor_sync(0xffffffff, pd, 1);
    pd += __shfl_xor_sync(0xffffffff, pd, 2);
    pd += __shfl_xor_sync(0xffffffff, pd, 4);
    if (lane == 0) bp[wid] = pd / (den + 1e-16f);
    __syncthreads();
    if (threadIdx.x == 0) {
        float s = 0.f;
#pragma unroll
        for (int j = 0; j < 8; j++) s += bp[j];
        atomicAdd(&g_out_acc, s);
        __threadfence();
        unsigned old = atomicAdd(&g_done, 1u);
        if (old == gridDim.x - 1) {
            float total = atomicExch(&g_out_acc, 0.f);
            float bwr = 0.f;
            for (int i = 0; i < 64; i++) bwr += b2[i] * Wr[i];
            out[0] = total * (1.0f / (float)N) + bwr + br[0];
            g_done = 0;
        }
    }
}

// ---------------------------------------------------------------------------
// Launch
// ---------------------------------------------------------------------------
extern "C" void kernel_launch(void* const* d_in, const int* in_sizes, int n_in,
                              void* d_out, int out_size) {
    const float* x      = (const float*)d_in[0];
    const void*  ei     = d_in[1];
    const float* W_rel  = (const float*)d_in[2];
    const float* b_rel  = (const float*)d_in[3];
    const float* W_root = (const float*)d_in[4];
    const float* W1     = (const float*)d_in[5];
    const float* a1s    = (const float*)d_in[6];
    const float* a1d    = (const float*)d_in[7];
    const float* b1     = (const float*)d_in[8];
    const float* W2     = (const float*)d_in[9];
    const float* a2s    = (const float*)d_in[10];
    const float* a2d    = (const float*)d_in[11];
    const float* b2     = (const float*)d_in[12];
    const float* Wr     = (const float*)d_in[13];
    const float* br     = (const float*)d_in[14];
    float* out          = (float*)d_out;

    float *p_nbr, *p_h, *p_h2;
    void *p_z1b, *p_z2b;
    cudaGetSymbolAddress((void**)&p_nbr, g_nbr);
    cudaGetSymbolAddress((void**)&p_h,   g_h);
    cudaGetSymbolAddress(&p_z1b, g_z1b);
    cudaGetSymbolAddress((void**)&p_h2,  g_h2);
    cudaGetSymbolAddress(&p_z2b, g_z2b);

    init_kernel<<<256, 256>>>((const int*)ei);

    hist_kernel<<<(E + 255) / 256, 256>>>(ei);
    scan_conv_kernel<<<1 + CONV_B, 1024>>>(x);
    fill_kernel<<<(E / 2 + 255) / 256, 256>>>();

    gather_nbr_kernel<<<(N * 32 + 255) / 256, 256>>>();
    {
        dim3 g((N + 127) / 128, 1);
        bf16_linear<128, 0><<<g, 256>>>(p_nbr, W_rel, 128, x, W_root, 128,
                                        b_rel, p_h, nullptr, nullptr, N, 128, 1);
    }
    {
        dim3 g((N + 127) / 128, 1);
        bf16_linear<64, 1><<<g, 256>>>(p_h, W1, 128, nullptr, nullptr, 0,
                                       nullptr, p_z1b, a1s, a1d, N, 64, 0);
    }
    gat1_fused<<<(N * 32 + 255) / 256, 256>>>(b1);

    {
        dim3 g((N + 127) / 128, 1);
        bf16_linear<64, 2><<<g, 256>>>(p_h2, W2, 64, nullptr, nullptr, 0,
                                       nullptr, p_z2b, a2s, a2d, N, 64, 0);
    }
    gat2_fused<<<N * 32 / 256, 256>>>(Wr, br, b2, out);
}

// round 15
// speedup vs baseline: 1.2021x; 1.0433x over previous
#include <cuda_runtime.h>
#include <cuda_bf16.h>
#include <math.h>
#include <stdint.h>

constexpr int N = 50000;
constexpr int E = 800000;

// ---------------------------------------------------------------------------
// Device scratch
// ---------------------------------------------------------------------------
__device__ __align__(16) uint32_t g_xb  [N * 64];  // x as bf16x2 (128 ch)
__device__ __align__(16) uint32_t g_nbrb[N * 64];  // nbr sums as bf16x2
__device__ __align__(16) uint32_t g_hb  [N * 64];  // h as bf16x2 (128 ch)
__device__ __align__(16) uint32_t g_z1b [N * 32];  // z1 as bf16x2 (64 ch)
__device__ __align__(16) uint32_t g_h2b [N * 32];  // h2 as bf16x2
__device__ __align__(16) uint32_t g_z2b [N * 32];  // z2 as bf16x2
__device__ __align__(16) float g_as1[N * 8];
__device__ __align__(16) float g_ad1[N * 8];
__device__ float g_as2[N];
__device__ float g_ad2[N];
__device__ float g_out_acc;          // reset by gat2 last block
__device__ unsigned g_done;          // reset by gat2 last block
__device__ int g_deg[N];
__device__ int g_off[N];
__device__ unsigned long long g_pack[E];
__device__ int g_csr[E];
__device__ int g_is64;

// ---------------------------------------------------------------------------
// Helpers
// ---------------------------------------------------------------------------
__device__ __forceinline__ float lrelu(float x) { return x > 0.f ? x : 0.2f * x; }
__device__ __forceinline__ float elu1(float x)  { return x > 0.f ? x : __expf(x) - 1.f; }

__device__ __forceinline__ uint32_t pack_bf16(float a, float b) {
    __nv_bfloat162 v = __float22bfloat162_rn(make_float2(a, b));
    return *reinterpret_cast<uint32_t*>(&v);
}
__device__ __forceinline__ float2 unpack_bf16(uint32_t u) {
    return __bfloat1622float2(*reinterpret_cast<__nv_bfloat162*>(&u));
}

// m16n8k16 bf16 MMA, fp32 accumulate
__device__ __forceinline__ void mma_bf16(float c[4], const uint4& a, const uint2& b) {
    asm volatile(
        "mma.sync.aligned.m16n8k16.row.col.f32.bf16.bf16.f32 "
        "{%0,%1,%2,%3}, {%4,%5,%6,%7}, {%8,%9}, {%0,%1,%2,%3};"
        : "+f"(c[0]), "+f"(c[1]), "+f"(c[2]), "+f"(c[3])
        : "r"(a.x), "r"(a.y), "r"(a.z), "r"(a.w), "r"(b.x), "r"(b.y));
}

__device__ __forceinline__ int edge_id(const void* ei, long long idx) {
    return g_is64 ? (int)((const long long*)ei)[idx] : ((const int*)ei)[idx];
}
__device__ __forceinline__ int edge_src(const void* ei, int e) { return edge_id(ei, e); }
__device__ __forceinline__ int edge_dst(const void* ei, int e) { return edge_id(ei, (long long)E + e); }

// ---------------------------------------------------------------------------
// init: zero counters + dtype detect (block 0)
// ---------------------------------------------------------------------------
__global__ void init_kernel(const int* ei) {
    int i = blockIdx.x * blockDim.x + threadIdx.x;
    int stride = gridDim.x * blockDim.x;
    for (int t = i; t < N; t += stride) { g_deg[t] = 0; g_as2[t] = 0.f; g_ad2[t] = 0.f; }
    if (blockIdx.x == 0) {
        __shared__ int any;
        if (threadIdx.x == 0) any = 0;
        __syncthreads();
        for (int t = threadIdx.x; t < 1024; t += blockDim.x)
            if (ei[2 * t + 1] != 0) atomicOr(&any, 1);
        __syncthreads();
        if (threadIdx.x == 0) g_is64 = any ? 0 : 1;
    }
}

// ---------------------------------------------------------------------------
// hist: rank capture + packed (src|dst|rank) payload
// ---------------------------------------------------------------------------
__global__ void hist_kernel(const void* __restrict__ ei) {
    int e = blockIdx.x * blockDim.x + threadIdx.x;
    if (e >= E) return;
    int s = edge_src(ei, e), d = edge_dst(ei, e);
    unsigned rank = atomicAdd(&g_deg[d], 1);
    g_pack[e] = (unsigned long long)(unsigned)s
              | ((unsigned long long)(unsigned)d << 16)
              | ((unsigned long long)rank << 32);
}

// ---------------------------------------------------------------------------
// scan (block 0) + x->bf16 convert (blocks >= 1, riding in the scan's shadow)
// ---------------------------------------------------------------------------
constexpr int CONV_B = (N * 64 / 8 + 1023) / 1024;   // 391 blocks of 1024 thr

__global__ void scan_conv_kernel(const float* __restrict__ x) {
    if (blockIdx.x > 0) {
        int idx = (((int)blockIdx.x - 1) * 1024 + threadIdx.x) * 8;
        if (idx >= N * 64) return;
        const float4* xin = (const float4*)(x + (size_t)idx * 2);
        float4 v0 = xin[0], v1 = xin[1], v2 = xin[2], v3 = xin[3];
        uint4 o0, o1;
        o0.x = pack_bf16(v0.x, v0.y); o0.y = pack_bf16(v0.z, v0.w);
        o0.z = pack_bf16(v1.x, v1.y); o0.w = pack_bf16(v1.z, v1.w);
        o1.x = pack_bf16(v2.x, v2.y); o1.y = pack_bf16(v2.z, v2.w);
        o1.z = pack_bf16(v3.x, v3.y); o1.w = pack_bf16(v3.z, v3.w);
        *(uint4*)&g_xb[idx]     = o0;
        *(uint4*)&g_xb[idx + 4] = o1;
        return;
    }
    __shared__ int wsum[32];
    __shared__ int s_carry;
    int tid = threadIdx.x, lane = tid & 31, wid = tid >> 5;
    if (tid == 0) s_carry = 0;
    __syncthreads();
    for (int base = 0; base < N; base += 1024) {
        int i = base + tid;
        int v = (i < N) ? g_deg[i] : 0;
        int s = v;
#pragma unroll
        for (int o = 1; o < 32; o <<= 1) {
            int u = __shfl_up_sync(0xffffffff, s, o);
            if (lane >= o) s += u;
        }
        if (lane == 31) wsum[wid] = s;
        __syncthreads();
        if (wid == 0) {
            int w = wsum[lane];
#pragma unroll
            for (int o = 1; o < 32; o <<= 1) {
                int u = __shfl_up_sync(0xffffffff, w, o);
                if (lane >= o) w += u;
            }
            wsum[lane] = w;
        }
        __syncthreads();
        int prev = (wid > 0) ? wsum[wid - 1] : 0;
        int carry = s_carry;
        if (i < N) g_off[i] = carry + prev + s - v;
        __syncthreads();
        if (tid == 1023) s_carry = carry + wsum[31];
        __syncthreads();
    }
}

// fill: 2 edges per thread, one 16B pack load
__global__ void fill_kernel() {
    int e = (blockIdx.x * blockDim.x + threadIdx.x) * 2;
    if (e >= E) return;
    ulonglong2 pp = *(const ulonglong2*)&g_pack[e];
    {
        unsigned long long p = pp.x;
        g_csr[g_off[(int)((p >> 16) & 0xffffu)] + (int)(p >> 32)] = (int)(p & 0xffffu);
    }
    {
        unsigned long long p = pp.y;
        g_csr[g_off[(int)((p >> 16) & 0xffffu)] + (int)(p >> 32)] = (int)(p & 0xffffu);
    }
}

// ---------------------------------------------------------------------------
// GraphConv gather: quarter-warp per edge, bf16 x, fp32 accum, bf16 out
// ---------------------------------------------------------------------------
__global__ __launch_bounds__(256, 6) void gather_nbr_kernel() {
    int gid = blockIdx.x * blockDim.x + threadIdx.x;
    int node = gid >> 5, lane = gid & 31;
    if (node >= N) return;
    int beg = g_off[node], deg = g_deg[node];
    const int q = lane >> 3, l8 = lane & 7;

    float acc[16];
#pragma unroll
    for (int j = 0; j < 16; j++) acc[j] = 0.f;

    int k = q;
    for (; k + 4 < deg; k += 8) {
        int s0 = g_csr[beg + k], s1 = g_csr[beg + k + 4];
        uint4 a0 = *(const uint4*)&g_xb[(size_t)s0 * 64 + l8 * 8];
        uint4 b0 = *(const uint4*)&g_xb[(size_t)s0 * 64 + l8 * 8 + 4];
        uint4 a1 = *(const uint4*)&g_xb[(size_t)s1 * 64 + l8 * 8];
        uint4 b1 = *(const uint4*)&g_xb[(size_t)s1 * 64 + l8 * 8 + 4];
        const uint32_t u0[8] = {a0.x,a0.y,a0.z,a0.w,b0.x,b0.y,b0.z,b0.w};
        const uint32_t u1[8] = {a1.x,a1.y,a1.z,a1.w,b1.x,b1.y,b1.z,b1.w};
#pragma unroll
        for (int j = 0; j < 8; j++) {
            float2 p0 = unpack_bf16(u0[j]), p1 = unpack_bf16(u1[j]);
            acc[j*2]   += p0.x + p1.x;
            acc[j*2+1] += p0.y + p1.y;
        }
    }
    if (k < deg) {
        int s = g_csr[beg + k];
        uint4 a = *(const uint4*)&g_xb[(size_t)s * 64 + l8 * 8];
        uint4 b = *(const uint4*)&g_xb[(size_t)s * 64 + l8 * 8 + 4];
        const uint32_t u[8] = {a.x,a.y,a.z,a.w,b.x,b.y,b.z,b.w};
#pragma unroll
        for (int j = 0; j < 8; j++) {
            float2 p = unpack_bf16(u[j]);
            acc[j*2] += p.x; acc[j*2+1] += p.y;
        }
    }
#pragma unroll
    for (int j = 0; j < 16; j++) {
        acc[j] += __shfl_xor_sync(0xffffffff, acc[j], 8);
        acc[j] += __shfl_xor_sync(0xffffffff, acc[j], 16);
    }
    if (q == 0) {
        uint32_t* dst = g_nbrb + (size_t)node * 64 + l8 * 8;
        uint4 o0, o1;
        o0.x = pack_bf16(acc[0],  acc[1]);  o0.y = pack_bf16(acc[2],  acc[3]);
        o0.z = pack_bf16(acc[4],  acc[5]);  o0.w = pack_bf16(acc[6],  acc[7]);
        o1.x = pack_bf16(acc[8],  acc[9]);  o1.y = pack_bf16(acc[10], acc[11]);
        o1.z = pack_bf16(acc[12], acc[13]); o1.w = pack_bf16(acc[14], acc[15]);
        *(uint4*)dst       = o0;
        *(uint4*)(dst + 4) = o1;
    }
}

// ---------------------------------------------------------------------------
// bf16 GEMM (m16n8k16), A operands pre-packed bf16x2 (pitch K/2 uints).
//   MODE 0: bf16 out + bias + ELU (gemm0)
//   MODE 1: bf16 out + per-head alpha (as1/ad1)
//   MODE 2: bf16 out + single-head alpha partials via atomicAdd
// ---------------------------------------------------------------------------
template<int BN, int MODE>
__global__ __launch_bounds__(256) void bf16_linear(
    const uint32_t* __restrict__ A1b, const float* __restrict__ Wa, int K1,
    const uint32_t* __restrict__ A2b, const float* __restrict__ Wb, int K2,
    const float* __restrict__ bias, uint32_t* __restrict__ Zb,
    const float* __restrict__ aS, const float* __restrict__ aD,
    int M, int NCOL)
{
    constexpr int NT = BN / 16;
    __shared__ __align__(16) uint32_t As[2][8][128];
    __shared__ __align__(16) uint32_t Bs[2][BN / 8][64];
    const int tid  = threadIdx.x;
    const int lane = tid & 31, warp = tid >> 5;
    const int wm = warp & 3, wn = warp >> 2;
    const int row0 = blockIdx.x * 128, c0 = blockIdx.y * BN;

    float acc[2][NT][4];
#pragma unroll
    for (int mt = 0; mt < 2; mt++)
#pragma unroll
        for (int nt = 0; nt < NT; nt++)
#pragma unroll
            for (int j = 0; j < 4; j++) acc[mt][nt][j] = 0.f;

    const int nk1 = K1 >> 5;
    const int nk2 = A2b ? (K2 >> 5) : 0;
    for (int t = 0; t < nk1 + nk2; t++) {
        const uint32_t* Ab; const float* W; int K, kb;
        if (t < nk1) { Ab = A1b; W = Wa; K = K1; kb = t << 5; }
        else         { Ab = A2b; W = Wb; K = K2; kb = (t - nk1) << 5; }
        __syncthreads();
        // stage A tile 128x32 (bf16 source, no conversion)
#pragma unroll
        for (int i = 0; i < 4; i++) {
            int idx = tid + i * 256;
            int m = idx >> 3, k4 = (idx & 7) << 2;
            uint2 u = make_uint2(0u, 0u);
            if (row0 + m < M)
                u = *(const uint2*)(Ab + (size_t)(row0 + m) * (K >> 1) + ((kb + k4) >> 1));
            int m16 = m >> 4, mm = m & 15, r = mm & 7, rr = mm >> 3;
            int slab = k4 >> 4, kk = k4 & 15;
            int c0l = (kk >> 1) & 3;
            int reg = rr + 2 * ((kk >> 3) & 1);
            As[slab][m16][(r * 4 + c0l) * 4 + reg]     = u.x;
            As[slab][m16][(r * 4 + c0l + 1) * 4 + reg] = u.y;
        }
        // stage W tile BNx32 (fp32 -> bf16)
#pragma unroll
        for (int i = 0; i < BN / 32; i++) {
            int idx = tid + i * 256;
            int n = idx >> 3, k4 = (idx & 7) << 2;
            float4 v = *(const float4*)(W + (size_t)(c0 + n) * K + kb + k4);
            uint32_t pair0 = pack_bf16(v.x, v.y);
            uint32_t pair1 = pack_bf16(v.z, v.w);
            int n8 = n >> 3, nn = n & 7;
            int slab = k4 >> 4, kk = k4 & 15;
            int c0l = (kk >> 1) & 3;
            int reg = (kk >> 3) & 1;
            Bs[slab][n8][(nn * 4 + c0l) * 2 + reg]     = pair0;
            Bs[slab][n8][(nn * 4 + c0l + 1) * 2 + reg] = pair1;
        }
        __syncthreads();
#pragma unroll
        for (int k16 = 0; k16 < 2; k16++) {
            uint4 a[2];
            uint2 b[NT];
            a[0] = *(const uint4*)&As[k16][wm * 2 + 0][lane * 4];
            a[1] = *(const uint4*)&As[k16][wm * 2 + 1][lane * 4];
#pragma unroll
            for (int nt = 0; nt < NT; nt++)
                b[nt] = *(const uint2*)&Bs[k16][wn * NT + nt][lane * 2];
#pragma unroll
            for (int mt = 0; mt < 2; mt++)
#pragma unroll
                for (int nt = 0; nt < NT; nt++)
                    mma_bf16(acc[mt][nt], a[mt], b[nt]);
        }
    }

    const int r = lane >> 2, cc = (lane & 3) * 2;
    const int zpitch = NCOL >> 1;
#pragma unroll
    for (int mt = 0; mt < 2; mt++) {
        int row  = row0 + (wm * 2 + mt) * 16 + r;
        int row2 = row + 8;
        float psl = 0.f, pdl = 0.f, psh = 0.f, pdh = 0.f;
#pragma unroll
        for (int nt = 0; nt < NT; nt++) {
            int col = c0 + (wn * NT + nt) * 8 + cc;
            float v0 = acc[mt][nt][0], v1 = acc[mt][nt][1];
            float v2 = acc[mt][nt][2], v3 = acc[mt][nt][3];
            if (MODE == 0) {
                float bx = bias[col], by = bias[col + 1];
                if (row < M)
                    Zb[(size_t)row * zpitch + (col >> 1)] =
                        pack_bf16(elu1(v0 + bx), elu1(v1 + by));
                if (row2 < M)
                    Zb[(size_t)row2 * zpitch + (col >> 1)] =
                        pack_bf16(elu1(v2 + bx), elu1(v3 + by));
            } else {
                if (row  < M) Zb[(size_t)row  * zpitch + (col >> 1)] = pack_bf16(v0, v1);
                if (row2 < M) Zb[(size_t)row2 * zpitch + (col >> 1)] = pack_bf16(v2, v3);
                float s0 = aS[col], s1 = aS[col + 1];
                float d0 = aD[col], d1 = aD[col + 1];
                if (MODE == 1) {
                    int h = wn * NT + nt;
                    float ps_lo = v0 * s0 + v1 * s1;
                    float pd_lo = v0 * d0 + v1 * d1;
                    float ps_hi = v2 * s0 + v3 * s1;
                    float pd_hi = v2 * d0 + v3 * d1;
                    ps_lo += __shfl_xor_sync(0xffffffff, ps_lo, 1);
                    ps_lo += __shfl_xor_sync(0xffffffff, ps_lo, 2);
                    pd_lo += __shfl_xor_sync(0xffffffff, pd_lo, 1);
                    pd_lo += __shfl_xor_sync(0xffffffff, pd_lo, 2);
                    ps_hi += __shfl_xor_sync(0xffffffff, ps_hi, 1);
                    ps_hi += __shfl_xor_sync(0xffffffff, ps_hi, 2);
                    pd_hi += __shfl_xor_sync(0xffffffff, pd_hi, 1);
                    pd_hi += __shfl_xor_sync(0xffffffff, pd_hi, 2);
                    if ((lane & 3) == 0) {
                        if (row  < M) { g_as1[(size_t)row  * 8 + h] = ps_lo; g_ad1[(size_t)row  * 8 + h] = pd_lo; }
                        if (row2 < M) { g_as1[(size_t)row2 * 8 + h] = ps_hi; g_ad1[(size_t)row2 * 8 + h] = pd_hi; }
                    }
                } else {
                    psl += v0 * s0 + v1 * s1;
                    pdl += v0 * d0 + v1 * d1;
                    psh += v2 * s0 + v3 * s1;
                    pdh += v2 * d0 + v3 * d1;
                }
            }
        }
        if (MODE == 2) {
            psl += __shfl_xor_sync(0xffffffff, psl, 1);
            psl += __shfl_xor_sync(0xffffffff, psl, 2);
            pdl += __shfl_xor_sync(0xffffffff, pdl, 1);
            pdl += __shfl_xor_sync(0xffffffff, pdl, 2);
            psh += __shfl_xor_sync(0xffffffff, psh, 1);
            psh += __shfl_xor_sync(0xffffffff, psh, 2);
            pdh += __shfl_xor_sync(0xffffffff, pdh, 1);
            pdh += __shfl_xor_sync(0xffffffff, pdh, 2);
            if ((lane & 3) == 0) {
                if (row  < M) { atomicAdd(&g_as2[row],  psl); atomicAdd(&g_ad2[row],  pdl); }
                if (row2 < M) { atomicAdd(&g_as2[row2], psh); atomicAdd(&g_ad2[row2], pdh); }
            }
        }
    }
}

// ---------------------------------------------------------------------------
// GAT1 fused: quarter-warp per edge (2 edges in flight), bf16 z, bf16 h2 out
// ---------------------------------------------------------------------------
__global__ void gat1_fused(const float* __restrict__ b1) {
    int gid = blockIdx.x * blockDim.x + threadIdx.x;
    int node = gid >> 5, lane = gid & 31;
    if (node >= N) return;
    int beg = g_off[node], deg = g_deg[node];
    const int q = lane >> 3, l8 = lane & 7;
    const float adh = g_ad1[(size_t)node * 8 + l8];

    float acc[8];
#pragma unroll
    for (int j = 0; j < 8; j++) acc[j] = 0.f;
    float den = 0.f;

    if (q == 0) {  // self-loop
        float w = __expf(lrelu(g_as1[(size_t)node * 8 + l8] + adh));
        uint4 u = *(const uint4*)&g_z1b[(size_t)node * 32 + l8 * 4];
        const uint32_t uu[4] = {u.x, u.y, u.z, u.w};
#pragma unroll
        for (int j = 0; j < 4; j++) {
            float2 p = unpack_bf16(uu[j]);
            acc[j*2] = w * p.x; acc[j*2+1] = w * p.y;
        }
        den = w;
    }
    int k = q;
    for (; k + 4 < deg; k += 8) {
        int s0 = g_csr[beg + k], s1 = g_csr[beg + k + 4];
        float w0 = __expf(lrelu(g_as1[(size_t)s0 * 8 + l8] + adh));
        float w1 = __expf(lrelu(g_as1[(size_t)s1 * 8 + l8] + adh));
        uint4 u0 = *(const uint4*)&g_z1b[(size_t)s0 * 32 + l8 * 4];
        uint4 u1 = *(const uint4*)&g_z1b[(size_t)s1 * 32 + l8 * 4];
        const uint32_t a0[4] = {u0.x, u0.y, u0.z, u0.w};
        const uint32_t a1[4] = {u1.x, u1.y, u1.z, u1.w};
#pragma unroll
        for (int j = 0; j < 4; j++) {
            float2 p0 = unpack_bf16(a0[j]), p1 = unpack_bf16(a1[j]);
            acc[j*2]   += w0 * p0.x + w1 * p1.x;
            acc[j*2+1] += w0 * p0.y + w1 * p1.y;
        }
        den += w0 + w1;
    }
    if (k < deg) {
        int s = g_csr[beg + k];
        float w = __expf(lrelu(g_as1[(size_t)s * 8 + l8] + adh));
        uint4 u = *(const uint4*)&g_z1b[(size_t)s * 32 + l8 * 4];
        const uint32_t uu[4] = {u.x, u.y, u.z, u.w};
#pragma unroll
        for (int j = 0; j < 4; j++) {
            float2 p = unpack_bf16(uu[j]);
            acc[j*2] += w * p.x; acc[j*2+1] += w * p.y;
        }
        den += w;
    }
#pragma unroll
    for (int j = 0; j < 8; j++) {
        acc[j] += __shfl_xor_sync(0xffffffff, acc[j], 8);
        acc[j] += __shfl_xor_sync(0xffffffff, acc[j], 16);
    }
    den += __shfl_xor_sync(0xffffffff, den, 8);
    den += __shfl_xor_sync(0xffffffff, den, 16);
    if (q == 0) {
        float rh = 1.f / (den + 1e-16f);
        const float* bb = b1 + l8 * 8;
        float4 b0 = *(const float4*)bb;
        float4 b4 = *(const float4*)(bb + 4);
        uint4 o;
        o.x = pack_bf16(elu1(acc[0] * rh + b0.x), elu1(acc[1] * rh + b0.y));
        o.y = pack_bf16(elu1(acc[2] * rh + b0.z), elu1(acc[3] * rh + b0.w));
        o.z = pack_bf16(elu1(acc[4] * rh + b4.x), elu1(acc[5] * rh + b4.y));
        o.w = pack_bf16(elu1(acc[6] * rh + b4.z), elu1(acc[7] * rh + b4.w));
        *(uint4*)&g_h2b[(size_t)node * 32 + l8 * 4] = o;
    }
}

// ---------------------------------------------------------------------------
// GAT2 fused + regression head; last block writes the final output
// ---------------------------------------------------------------------------
__global__ void gat2_fused(const float* __restrict__ Wr, const float* __restrict__ br,
                           const float* __restrict__ b2, float* __restrict__ out) {
    __shared__ float bp[8];
    int gid = blockIdx.x * blockDim.x + threadIdx.x;
    int node = gid >> 5, lane = gid & 31, wid = threadIdx.x >> 5;
    int beg = g_off[node], deg = g_deg[node];
    const int q = lane >> 3, l8 = lane & 7;
    const float adn = g_ad2[node];

    float acc[8];
#pragma unroll
    for (int j = 0; j < 8; j++) acc[j] = 0.f;
    float den = 0.f;

    if (q == 0) {
        float w = __expf(lrelu(g_as2[node] + adn));
        uint4 u = *(const uint4*)&g_z2b[(size_t)node * 32 + l8 * 4];
        const uint32_t uu[4] = {u.x, u.y, u.z, u.w};
#pragma unroll
        for (int j = 0; j < 4; j++) {
            float2 p = unpack_bf16(uu[j]);
            acc[j*2] = w * p.x; acc[j*2+1] = w * p.y;
        }
        den = w;
    }
    int k = q;
    for (; k + 4 < deg; k += 8) {
        int s0 = g_csr[beg + k], s1 = g_csr[beg + k + 4];
        float w0 = __expf(lrelu(g_as2[s0] + adn));
        float w1 = __expf(lrelu(g_as2[s1] + adn));
        uint4 u0 = *(const uint4*)&g_z2b[(size_t)s0 * 32 + l8 * 4];
        uint4 u1 = *(const uint4*)&g_z2b[(size_t)s1 * 32 + l8 * 4];
        const uint32_t a0[4] = {u0.x, u0.y, u0.z, u0.w};
        const uint32_t a1[4] = {u1.x, u1.y, u1.z, u1.w};
#pragma unroll
        for (int j = 0; j < 4; j++) {
            float2 p0 = unpack_bf16(a0[j]), p1 = unpack_bf16(a1[j]);
            acc[j*2]   += w0 * p0.x + w1 * p1.x;
            acc[j*2+1] += w0 * p0.y + w1 * p1.y;
        }
        den += w0 + w1;
    }
    if (k < deg) {
        int s = g_csr[beg + k];
        float w = __expf(lrelu(g_as2[s] + adn));
        uint4 u = *(const uint4*)&g_z2b[(size_t)s * 32 + l8 * 4];
        const uint32_t uu[4] = {u.x, u.y, u.z, u.w};
#pragma unroll
        for (int j = 0; j < 4; j++) {
            float2 p = unpack_bf16(uu[j]);
            acc[j*2] += w * p.x; acc[j*2+1] += w * p.y;
        }
        den += w;
    }
#pragma unroll
    for (int j = 0; j < 8; j++) {
        acc[j] += __shfl_xor_sync(0xffffffff, acc[j], 8);
        acc[j] += __shfl_xor_sync(0xffffffff, acc[j], 16);
    }
    den += __shfl_xor_sync(0xffffffff, den, 8);
    den += __shfl_xor_sync(0xffffffff, den, 16);

    float pd = 0.f;
    const float* wp = Wr + l8 * 8;
#pragma unroll
    for (int j = 0; j < 8; j++) pd += acc[j] * wp[j];
    pd += __shfl_xor_sync(0xffffffff, pd, 1);
    pd += __shfl_xor_sync(0xffffffff, pd, 2);
    pd += __shfl_xor_sync(0xffffffff, pd, 4);
    if (lane == 0) bp[wid] = pd / (den + 1e-16f);
    __syncthreads();
    if (threadIdx.x == 0) {
        float s = 0.f;
#pragma unroll
        for (int j = 0; j < 8; j++) s += bp[j];
        atomicAdd(&g_out_acc, s);
        __threadfence();
        unsigned old = atomicAdd(&g_done, 1u);
        if (old == gridDim.x - 1) {
            float total = atomicExch(&g_out_acc, 0.f);
            float bwr = 0.f;
            for (int i = 0; i < 64; i++) bwr += b2[i] * Wr[i];
            out[0] = total * (1.0f / (float)N) + bwr + br[0];
            g_done = 0;
        }
    }
}

// ---------------------------------------------------------------------------
// Launch
// ---------------------------------------------------------------------------
extern "C" void kernel_launch(void* const* d_in, const int* in_sizes, int n_in,
                              void* d_out, int out_size) {
    const float* x      = (const float*)d_in[0];
    const void*  ei     = d_in[1];
    const float* W_rel  = (const float*)d_in[2];
    const float* b_rel  = (const float*)d_in[3];
    const float* W_root = (const float*)d_in[4];
    const float* W1     = (const float*)d_in[5];
    const float* a1s    = (const float*)d_in[6];
    const float* a1d    = (const float*)d_in[7];
    const float* b1     = (const float*)d_in[8];
    const float* W2     = (const float*)d_in[9];
    const float* a2s    = (const float*)d_in[10];
    const float* a2d    = (const float*)d_in[11];
    const float* b2     = (const float*)d_in[12];
    const float* Wr     = (const float*)d_in[13];
    const float* br     = (const float*)d_in[14];
    float* out          = (float*)d_out;

    uint32_t *p_xb, *p_nbrb, *p_hb, *p_z1b, *p_h2b, *p_z2b;
    cudaGetSymbolAddress((void**)&p_xb,   g_xb);
    cudaGetSymbolAddress((void**)&p_nbrb, g_nbrb);
    cudaGetSymbolAddress((void**)&p_hb,   g_hb);
    cudaGetSymbolAddress((void**)&p_z1b,  g_z1b);
    cudaGetSymbolAddress((void**)&p_h2b,  g_h2b);
    cudaGetSymbolAddress((void**)&p_z2b,  g_z2b);

    init_kernel<<<256, 256>>>((const int*)ei);

    hist_kernel<<<(E + 255) / 256, 256>>>(ei);
    scan_conv_kernel<<<1 + CONV_B, 1024>>>(x);
    fill_kernel<<<(E / 2 + 255) / 256, 256>>>();

    gather_nbr_kernel<<<(N * 32 + 255) / 256, 256>>>();
    {
        dim3 g((N + 127) / 128, 1);
        bf16_linear<128, 0><<<g, 256>>>(p_nbrb, W_rel, 128, p_xb, W_root, 128,
                                        b_rel, p_hb, nullptr, nullptr, N, 128);
    }
    {
        dim3 g((N + 127) / 128, 1);
        bf16_linear<64, 1><<<g, 256>>>(p_hb, W1, 128, nullptr, nullptr, 0,
                                       nullptr, p_z1b, a1s, a1d, N, 64);
    }
    gat1_fused<<<(N * 32 + 255) / 256, 256>>>(b1);

    {
        dim3 g((N + 127) / 128, 1);
        bf16_linear<64, 2><<<g, 256>>>(p_h2b, W2, 64, nullptr, nullptr, 0,
                                       nullptr, p_z2b, a2s, a2d, N, 64);
    }
    gat2_fused<<<N * 32 / 256, 256>>>(Wr, br, b2, out);
}

// round 16
// speedup vs baseline: 1.2306x; 1.0237x over previous
#include <cuda_runtime.h>
#include <cuda_bf16.h>
#include <math.h>
#include <stdint.h>

constexpr int N = 50000;
constexpr int E = 800000;

// ---------------------------------------------------------------------------
// Device scratch
// ---------------------------------------------------------------------------
__device__ __align__(16) uint32_t g_xb  [N * 64];  // x as bf16x2 (128 ch)
__device__ __align__(16) uint32_t g_nbrb[N * 64];  // nbr sums as bf16x2
__device__ __align__(16) uint32_t g_z1b [N * 32];  // z1 as bf16x2 (64 ch)
__device__ __align__(16) uint32_t g_h2b [N * 32];  // h2 as bf16x2
__device__ __align__(16) uint32_t g_z2b [N * 32];  // z2 as bf16x2
__device__ __align__(16) float g_as1[N * 8];
__device__ __align__(16) float g_ad1[N * 8];
__device__ float g_as2[N];
__device__ float g_ad2[N];
__device__ float g_out_acc;          // reset by gat2 last block
__device__ unsigned g_done;          // reset by gat2 last block
__device__ int g_deg[N];
__device__ int g_off[N];
__device__ unsigned long long g_pack[E];
__device__ int g_csr[E];
__device__ int g_is64;

// ---------------------------------------------------------------------------
// Helpers
// ---------------------------------------------------------------------------
__device__ __forceinline__ float lrelu(float x) { return x > 0.f ? x : 0.2f * x; }
__device__ __forceinline__ float elu1(float x)  { return x > 0.f ? x : __expf(x) - 1.f; }

__device__ __forceinline__ uint32_t pack_bf16(float a, float b) {
    __nv_bfloat162 v = __float22bfloat162_rn(make_float2(a, b));
    return *reinterpret_cast<uint32_t*>(&v);
}
__device__ __forceinline__ float2 unpack_bf16(uint32_t u) {
    return __bfloat1622float2(*reinterpret_cast<__nv_bfloat162*>(&u));
}

// m16n8k16 bf16 MMA, fp32 accumulate
__device__ __forceinline__ void mma_bf16(float c[4], const uint4& a, const uint2& b) {
    asm volatile(
        "mma.sync.aligned.m16n8k16.row.col.f32.bf16.bf16.f32 "
        "{%0,%1,%2,%3}, {%4,%5,%6,%7}, {%8,%9}, {%0,%1,%2,%3};"
        : "+f"(c[0]), "+f"(c[1]), "+f"(c[2]), "+f"(c[3])
        : "r"(a.x), "r"(a.y), "r"(a.z), "r"(a.w), "r"(b.x), "r"(b.y));
}

__device__ __forceinline__ int edge_id(const void* ei, long long idx) {
    return g_is64 ? (int)((const long long*)ei)[idx] : ((const int*)ei)[idx];
}
__device__ __forceinline__ int edge_src(const void* ei, int e) { return edge_id(ei, e); }
__device__ __forceinline__ int edge_dst(const void* ei, int e) { return edge_id(ei, (long long)E + e); }

// ---------------------------------------------------------------------------
// init: zero counters + dtype detect (block 0)
// ---------------------------------------------------------------------------
__global__ void init_kernel(const int* ei) {
    int i = blockIdx.x * blockDim.x + threadIdx.x;
    int stride = gridDim.x * blockDim.x;
    for (int t = i; t < N; t += stride) { g_deg[t] = 0; g_as2[t] = 0.f; g_ad2[t] = 0.f; }
    if (blockIdx.x == 0) {
        __shared__ int any;
        if (threadIdx.x == 0) any = 0;
        __syncthreads();
        for (int t = threadIdx.x; t < 1024; t += blockDim.x)
            if (ei[2 * t + 1] != 0) atomicOr(&any, 1);
        __syncthreads();
        if (threadIdx.x == 0) g_is64 = any ? 0 : 1;
    }
}

// ---------------------------------------------------------------------------
// hist: rank capture + packed (src|dst|rank) payload
// ---------------------------------------------------------------------------
__global__ void hist_kernel(const void* __restrict__ ei) {
    int e = blockIdx.x * blockDim.x + threadIdx.x;
    if (e >= E) return;
    int s = edge_src(ei, e), d = edge_dst(ei, e);
    unsigned rank = atomicAdd(&g_deg[d], 1);
    g_pack[e] = (unsigned long long)(unsigned)s
              | ((unsigned long long)(unsigned)d << 16)
              | ((unsigned long long)rank << 32);
}

// ---------------------------------------------------------------------------
// scan (block 0) + x->bf16 convert (blocks >= 1, riding in the scan's shadow)
// ---------------------------------------------------------------------------
constexpr int CONV_B = (N * 64 / 8 + 1023) / 1024;   // 391 blocks of 1024 thr

__global__ void scan_conv_kernel(const float* __restrict__ x) {
    if (blockIdx.x > 0) {
        int idx = (((int)blockIdx.x - 1) * 1024 + threadIdx.x) * 8;
        if (idx >= N * 64) return;
        const float4* xin = (const float4*)(x + (size_t)idx * 2);
        float4 v0 = xin[0], v1 = xin[1], v2 = xin[2], v3 = xin[3];
        uint4 o0, o1;
        o0.x = pack_bf16(v0.x, v0.y); o0.y = pack_bf16(v0.z, v0.w);
        o0.z = pack_bf16(v1.x, v1.y); o0.w = pack_bf16(v1.z, v1.w);
        o1.x = pack_bf16(v2.x, v2.y); o1.y = pack_bf16(v2.z, v2.w);
        o1.z = pack_bf16(v3.x, v3.y); o1.w = pack_bf16(v3.z, v3.w);
        *(uint4*)&g_xb[idx]     = o0;
        *(uint4*)&g_xb[idx + 4] = o1;
        return;
    }
    __shared__ int wsum[32];
    __shared__ int s_carry;
    int tid = threadIdx.x, lane = tid & 31, wid = tid >> 5;
    if (tid == 0) s_carry = 0;
    __syncthreads();
    for (int base = 0; base < N; base += 1024) {
        int i = base + tid;
        int v = (i < N) ? g_deg[i] : 0;
        int s = v;
#pragma unroll
        for (int o = 1; o < 32; o <<= 1) {
            int u = __shfl_up_sync(0xffffffff, s, o);
            if (lane >= o) s += u;
        }
        if (lane == 31) wsum[wid] = s;
        __syncthreads();
        if (wid == 0) {
            int w = wsum[lane];
#pragma unroll
            for (int o = 1; o < 32; o <<= 1) {
                int u = __shfl_up_sync(0xffffffff, w, o);
                if (lane >= o) w += u;
            }
            wsum[lane] = w;
        }
        __syncthreads();
        int prev = (wid > 0) ? wsum[wid - 1] : 0;
        int carry = s_carry;
        if (i < N) g_off[i] = carry + prev + s - v;
        __syncthreads();
        if (tid == 1023) s_carry = carry + wsum[31];
        __syncthreads();
    }
}

// fill: 2 edges per thread, one 16B pack load
__global__ void fill_kernel() {
    int e = (blockIdx.x * blockDim.x + threadIdx.x) * 2;
    if (e >= E) return;
    ulonglong2 pp = *(const ulonglong2*)&g_pack[e];
    {
        unsigned long long p = pp.x;
        g_csr[g_off[(int)((p >> 16) & 0xffffu)] + (int)(p >> 32)] = (int)(p & 0xffffu);
    }
    {
        unsigned long long p = pp.y;
        g_csr[g_off[(int)((p >> 16) & 0xffffu)] + (int)(p >> 32)] = (int)(p & 0xffffu);
    }
}

// ---------------------------------------------------------------------------
// GraphConv gather: quarter-warp per edge, bf16 x, fp32 accum, bf16 out
// ---------------------------------------------------------------------------
__global__ __launch_bounds__(256, 6) void gather_nbr_kernel() {
    int gid = blockIdx.x * blockDim.x + threadIdx.x;
    int node = gid >> 5, lane = gid & 31;
    if (node >= N) return;
    int beg = g_off[node], deg = g_deg[node];
    const int q = lane >> 3, l8 = lane & 7;

    float acc[16];
#pragma unroll
    for (int j = 0; j < 16; j++) acc[j] = 0.f;

    int k = q;
    for (; k + 4 < deg; k += 8) {
        int s0 = g_csr[beg + k], s1 = g_csr[beg + k + 4];
        uint4 a0 = *(const uint4*)&g_xb[(size_t)s0 * 64 + l8 * 8];
        uint4 b0 = *(const uint4*)&g_xb[(size_t)s0 * 64 + l8 * 8 + 4];
        uint4 a1 = *(const uint4*)&g_xb[(size_t)s1 * 64 + l8 * 8];
        uint4 b1 = *(const uint4*)&g_xb[(size_t)s1 * 64 + l8 * 8 + 4];
        const uint32_t u0[8] = {a0.x,a0.y,a0.z,a0.w,b0.x,b0.y,b0.z,b0.w};
        const uint32_t u1[8] = {a1.x,a1.y,a1.z,a1.w,b1.x,b1.y,b1.z,b1.w};
#pragma unroll
        for (int j = 0; j < 8; j++) {
            float2 p0 = unpack_bf16(u0[j]), p1 = unpack_bf16(u1[j]);
            acc[j*2]   += p0.x + p1.x;
            acc[j*2+1] += p0.y + p1.y;
        }
    }
    if (k < deg) {
        int s = g_csr[beg + k];
        uint4 a = *(const uint4*)&g_xb[(size_t)s * 64 + l8 * 8];
        uint4 b = *(const uint4*)&g_xb[(size_t)s * 64 + l8 * 8 + 4];
        const uint32_t u[8] = {a.x,a.y,a.z,a.w,b.x,b.y,b.z,b.w};
#pragma unroll
        for (int j = 0; j < 8; j++) {
            float2 p = unpack_bf16(u[j]);
            acc[j*2] += p.x; acc[j*2+1] += p.y;
        }
    }
#pragma unroll
    for (int j = 0; j < 16; j++) {
        acc[j] += __shfl_xor_sync(0xffffffff, acc[j], 8);
        acc[j] += __shfl_xor_sync(0xffffffff, acc[j], 16);
    }
    if (q == 0) {
        uint32_t* dst = g_nbrb + (size_t)node * 64 + l8 * 8;
        uint4 o0, o1;
        o0.x = pack_bf16(acc[0],  acc[1]);  o0.y = pack_bf16(acc[2],  acc[3]);
        o0.z = pack_bf16(acc[4],  acc[5]);  o0.w = pack_bf16(acc[6],  acc[7]);
        o1.x = pack_bf16(acc[8],  acc[9]);  o1.y = pack_bf16(acc[10], acc[11]);
        o1.z = pack_bf16(acc[12], acc[13]); o1.w = pack_bf16(acc[14], acc[15]);
        *(uint4*)dst       = o0;
        *(uint4*)(dst + 4) = o1;
    }
}

// ---------------------------------------------------------------------------
// FUSED gemm0+gemm1:
//   stage1: h = elu(nbr@Wrel^T + x@Wroot^T + b_rel)  -> Hs (smem, frag layout)
//   stage2: z1 = h@W1^T -> g_z1b ; alpha1 -> g_as1/g_ad1
// BM=128, 256 threads. Bit-identical to the former two-kernel path.
// ---------------------------------------------------------------------------
__global__ __launch_bounds__(256) void fused_gemm01(
    const uint32_t* __restrict__ A1b, const float* __restrict__ Wa,
    const uint32_t* __restrict__ A2b, const float* __restrict__ Wb,
    const float* __restrict__ bias, const float* __restrict__ W1,
    uint32_t* __restrict__ Zb, const float* __restrict__ aS,
    const float* __restrict__ aD, int M)
{
    __shared__ __align__(16) uint32_t As[2][8][128];    // 8 KB
    __shared__ __align__(16) uint32_t Bs[2][16][64];    // 8 KB
    __shared__ __align__(16) uint32_t Hs[8][8][128];    // 32 KB, h frag layout
    const int tid  = threadIdx.x;
    const int lane = tid & 31, warp = tid >> 5;
    const int wm = warp & 3, wn = warp >> 2;            // 4 m-warps x 2 n-warps
    const int row0 = blockIdx.x * 128;
    const int r = lane >> 2, cc = (lane & 3) * 2;

    // ---------------- stage 1 ----------------
    {
        float acc1[2][8][4];
#pragma unroll
        for (int mt = 0; mt < 2; mt++)
#pragma unroll
            for (int nt = 0; nt < 8; nt++)
#pragma unroll
                for (int j = 0; j < 4; j++) acc1[mt][nt][j] = 0.f;

        for (int t = 0; t < 8; t++) {
            const uint32_t* Ab = (t < 4) ? A1b : A2b;
            const float* W     = (t < 4) ? Wa  : Wb;
            int kb = (t & 3) << 5;
            __syncthreads();
#pragma unroll
            for (int i = 0; i < 4; i++) {
                int idx = tid + i * 256;
                int m = idx >> 3, k4 = (idx & 7) << 2;
                uint2 u = make_uint2(0u, 0u);
                if (row0 + m < M)
                    u = *(const uint2*)(Ab + (size_t)(row0 + m) * 64 + ((kb + k4) >> 1));
                int m16 = m >> 4, mm = m & 15, rr = mm >> 3, rq = mm & 7;
                int slab = k4 >> 4, kk = k4 & 15;
                int c0l = (kk >> 1) & 3;
                int reg = rr + 2 * ((kk >> 3) & 1);
                As[slab][m16][(rq * 4 + c0l) * 4 + reg]     = u.x;
                As[slab][m16][(rq * 4 + c0l + 1) * 4 + reg] = u.y;
            }
#pragma unroll
            for (int i = 0; i < 4; i++) {
                int idx = tid + i * 256;
                int n = idx >> 3, k4 = (idx & 7) << 2;
                float4 v = *(const float4*)(W + (size_t)n * 128 + kb + k4);
                uint32_t p0 = pack_bf16(v.x, v.y), p1 = pack_bf16(v.z, v.w);
                int n8 = n >> 3, nn = n & 7;
                int slab = k4 >> 4, kk = k4 & 15;
                int c0l = (kk >> 1) & 3;
                int reg = (kk >> 3) & 1;
                Bs[slab][n8][(nn * 4 + c0l) * 2 + reg]     = p0;
                Bs[slab][n8][(nn * 4 + c0l + 1) * 2 + reg] = p1;
            }
            __syncthreads();
#pragma unroll
            for (int k16 = 0; k16 < 2; k16++) {
                uint4 a[2];
                uint2 b[8];
                a[0] = *(const uint4*)&As[k16][wm * 2 + 0][lane * 4];
                a[1] = *(const uint4*)&As[k16][wm * 2 + 1][lane * 4];
#pragma unroll
                for (int nt = 0; nt < 8; nt++)
                    b[nt] = *(const uint2*)&Bs[k16][wn * 8 + nt][lane * 2];
#pragma unroll
                for (int mt = 0; mt < 2; mt++)
#pragma unroll
                    for (int nt = 0; nt < 8; nt++)
                        mma_bf16(acc1[mt][nt], a[mt], b[nt]);
            }
        }

        // epilogue 1: bias + ELU + bf16-pack into Hs fragment layout
        __syncthreads();   // all stage-1 MMA reads of As/Bs done before stage-2 reuses Bs
#pragma unroll
        for (int mt = 0; mt < 2; mt++) {
            int m16 = wm * 2 + mt;
#pragma unroll
            for (int nt = 0; nt < 8; nt++) {
                int col = (wn * 8 + nt) * 8 + cc;
                float bx = bias[col], by = bias[col + 1];
                uint32_t plo = pack_bf16(elu1(acc1[mt][nt][0] + bx), elu1(acc1[mt][nt][1] + by));
                uint32_t phi = pack_bf16(elu1(acc1[mt][nt][2] + bx), elu1(acc1[mt][nt][3] + by));
                int slab = col >> 4, kk = col & 15;
                int c0l = (kk >> 1) & 3;
                int kreg = 2 * ((kk >> 3) & 1);
                Hs[slab][m16][(r * 4 + c0l) * 4 + kreg]     = plo;   // rows r (rr=0)
                Hs[slab][m16][(r * 4 + c0l) * 4 + kreg + 1] = phi;   // rows r+8 (rr=1)
            }
        }
    }
    __syncthreads();

    // ---------------- stage 2: z1 = h @ W1^T (BN=64) ----------------
    float acc2[2][4][4];
#pragma unroll
    for (int mt = 0; mt < 2; mt++)
#pragma unroll
        for (int nt = 0; nt < 4; nt++)
#pragma unroll
            for (int j = 0; j < 4; j++) acc2[mt][nt][j] = 0.f;

    for (int t2 = 0; t2 < 4; t2++) {
        int kb = t2 << 5;
        __syncthreads();
#pragma unroll
        for (int i = 0; i < 2; i++) {
            int idx = tid + i * 256;
            int n = idx >> 3, k4 = (idx & 7) << 2;
            float4 v = *(const float4*)(W1 + (size_t)n * 128 + kb + k4);
            uint32_t p0 = pack_bf16(v.x, v.y), p1 = pack_bf16(v.z, v.w);
            int n8 = n >> 3, nn = n & 7;
            int slab = k4 >> 4, kk = k4 & 15;
            int c0l = (kk >> 1) & 3;
            int reg = (kk >> 3) & 1;
            Bs[slab][n8][(nn * 4 + c0l) * 2 + reg]     = p0;
            Bs[slab][n8][(nn * 4 + c0l + 1) * 2 + reg] = p1;
        }
        __syncthreads();
#pragma unroll
        for (int k16 = 0; k16 < 2; k16++) {
            int gs = t2 * 2 + k16;
            uint4 a[2];
            uint2 b[4];
            a[0] = *(const uint4*)&Hs[gs][wm * 2 + 0][lane * 4];
            a[1] = *(const uint4*)&Hs[gs][wm * 2 + 1][lane * 4];
#pragma unroll
            for (int nt = 0; nt < 4; nt++)
                b[nt] = *(const uint2*)&Bs[k16][wn * 4 + nt][lane * 2];
#pragma unroll
            for (int mt = 0; mt < 2; mt++)
#pragma unroll
                for (int nt = 0; nt < 4; nt++)
                    mma_bf16(acc2[mt][nt], a[mt], b[nt]);
        }
    }

    // epilogue 2: z1b store + per-head alpha (identical to old MODE 1)
#pragma unroll
    for (int mt = 0; mt < 2; mt++) {
        int row  = row0 + (wm * 2 + mt) * 16 + r;
        int row2 = row + 8;
#pragma unroll
        for (int nt = 0; nt < 4; nt++) {
            int col = (wn * 4 + nt) * 8 + cc;
            float v0 = acc2[mt][nt][0], v1 = acc2[mt][nt][1];
            float v2 = acc2[mt][nt][2], v3 = acc2[mt][nt][3];
            if (row  < M) Zb[(size_t)row  * 32 + (col >> 1)] = pack_bf16(v0, v1);
            if (row2 < M) Zb[(size_t)row2 * 32 + (col >> 1)] = pack_bf16(v2, v3);
            float s0 = aS[col], s1 = aS[col + 1];
            float d0 = aD[col], d1 = aD[col + 1];
            int h = wn * 4 + nt;
            float ps_lo = v0 * s0 + v1 * s1;
            float pd_lo = v0 * d0 + v1 * d1;
            float ps_hi = v2 * s0 + v3 * s1;
            float pd_hi = v2 * d0 + v3 * d1;
            ps_lo += __shfl_xor_sync(0xffffffff, ps_lo, 1);
            ps_lo += __shfl_xor_sync(0xffffffff, ps_lo, 2);
            pd_lo += __shfl_xor_sync(0xffffffff, pd_lo, 1);
            pd_lo += __shfl_xor_sync(0xffffffff, pd_lo, 2);
            ps_hi += __shfl_xor_sync(0xffffffff, ps_hi, 1);
            ps_hi += __shfl_xor_sync(0xffffffff, ps_hi, 2);
            pd_hi += __shfl_xor_sync(0xffffffff, pd_hi, 1);
            pd_hi += __shfl_xor_sync(0xffffffff, pd_hi, 2);
            if ((lane & 3) == 0) {
                if (row  < M) { g_as1[(size_t)row  * 8 + h] = ps_lo; g_ad1[(size_t)row  * 8 + h] = pd_lo; }
                if (row2 < M) { g_as1[(size_t)row2 * 8 + h] = ps_hi; g_ad1[(size_t)row2 * 8 + h] = pd_hi; }
            }
        }
    }
}

// ---------------------------------------------------------------------------
// bf16 GEMM (m16n8k16), MODE 2 only: bf16 out + single-head alpha atomics
// ---------------------------------------------------------------------------
template<int BN>
__global__ __launch_bounds__(256) void bf16_linear2(
    const uint32_t* __restrict__ A1b, const float* __restrict__ Wa, int K1,
    uint32_t* __restrict__ Zb, const float* __restrict__ aS,
    const float* __restrict__ aD, int M, int NCOL)
{
    constexpr int NT = BN / 16;
    __shared__ __align__(16) uint32_t As[2][8][128];
    __shared__ __align__(16) uint32_t Bs[2][BN / 8][64];
    const int tid  = threadIdx.x;
    const int lane = tid & 31, warp = tid >> 5;
    const int wm = warp & 3, wn = warp >> 2;
    const int row0 = blockIdx.x * 128, c0 = blockIdx.y * BN;

    float acc[2][NT][4];
#pragma unroll
    for (int mt = 0; mt < 2; mt++)
#pragma unroll
        for (int nt = 0; nt < NT; nt++)
#pragma unroll
            for (int j = 0; j < 4; j++) acc[mt][nt][j] = 0.f;

    const int nk1 = K1 >> 5;
    for (int t = 0; t < nk1; t++) {
        int kb = t << 5;
        __syncthreads();
#pragma unroll
        for (int i = 0; i < 4; i++) {
            int idx = tid + i * 256;
            int m = idx >> 3, k4 = (idx & 7) << 2;
            uint2 u = make_uint2(0u, 0u);
            if (row0 + m < M)
                u = *(const uint2*)(A1b + (size_t)(row0 + m) * (K1 >> 1) + ((kb + k4) >> 1));
            int m16 = m >> 4, mm = m & 15, rr = mm >> 3, rq = mm & 7;
            int slab = k4 >> 4, kk = k4 & 15;
            int c0l = (kk >> 1) & 3;
            int reg = rr + 2 * ((kk >> 3) & 1);
            As[slab][m16][(rq * 4 + c0l) * 4 + reg]     = u.x;
            As[slab][m16][(rq * 4 + c0l + 1) * 4 + reg] = u.y;
        }
#pragma unroll
        for (int i = 0; i < BN / 32; i++) {
            int idx = tid + i * 256;
            int n = idx >> 3, k4 = (idx & 7) << 2;
            float4 v = *(const float4*)(Wa + (size_t)(c0 + n) * K1 + kb + k4);
            uint32_t p0 = pack_bf16(v.x, v.y), p1 = pack_bf16(v.z, v.w);
            int n8 = n >> 3, nn = n & 7;
            int slab = k4 >> 4, kk = k4 & 15;
            int c0l = (kk >> 1) & 3;
            int reg = (kk >> 3) & 1;
            Bs[slab][n8][(nn * 4 + c0l) * 2 + reg]     = p0;
            Bs[slab][n8][(nn * 4 + c0l + 1) * 2 + reg] = p1;
        }
        __syncthreads();
#pragma unroll
        for (int k16 = 0; k16 < 2; k16++) {
            uint4 a[2];
            uint2 b[NT];
            a[0] = *(const uint4*)&As[k16][wm * 2 + 0][lane * 4];
            a[1] = *(const uint4*)&As[k16][wm * 2 + 1][lane * 4];
#pragma unroll
            for (int nt = 0; nt < NT; nt++)
                b[nt] = *(const uint2*)&Bs[k16][wn * NT + nt][lane * 2];
#pragma unroll
            for (int mt = 0; mt < 2; mt++)
#pragma unroll
                for (int nt = 0; nt < NT; nt++)
                    mma_bf16(acc[mt][nt], a[mt], b[nt]);
        }
    }

    const int r = lane >> 2, cc = (lane & 3) * 2;
    const int zpitch = NCOL >> 1;
#pragma unroll
    for (int mt = 0; mt < 2; mt++) {
        int row  = row0 + (wm * 2 + mt) * 16 + r;
        int row2 = row + 8;
        float psl = 0.f, pdl = 0.f, psh = 0.f, pdh = 0.f;
#pragma unroll
        for (int nt = 0; nt < NT; nt++) {
            int col = c0 + (wn * NT + nt) * 8 + cc;
            float v0 = acc[mt][nt][0], v1 = acc[mt][nt][1];
            float v2 = acc[mt][nt][2], v3 = acc[mt][nt][3];
            if (row  < M) Zb[(size_t)row  * zpitch + (col >> 1)] = pack_bf16(v0, v1);
            if (row2 < M) Zb[(size_t)row2 * zpitch + (col >> 1)] = pack_bf16(v2, v3);
            float s0 = aS[col], s1 = aS[col + 1];
            float d0 = aD[col], d1 = aD[col + 1];
            psl += v0 * s0 + v1 * s1;
            pdl += v0 * d0 + v1 * d1;
            psh += v2 * s0 + v3 * s1;
            pdh += v2 * d0 + v3 * d1;
        }
        psl += __shfl_xor_sync(0xffffffff, psl, 1);
        psl += __shfl_xor_sync(0xffffffff, psl, 2);
        pdl += __shfl_xor_sync(0xffffffff, pdl, 1);
        pdl += __shfl_xor_sync(0xffffffff, pdl, 2);
        psh += __shfl_xor_sync(0xffffffff, psh, 1);
        psh += __shfl_xor_sync(0xffffffff, psh, 2);
        pdh += __shfl_xor_sync(0xffffffff, pdh, 1);
        pdh += __shfl_xor_sync(0xffffffff, pdh, 2);
        if ((lane & 3) == 0) {
            if (row  < M) { atomicAdd(&g_as2[row],  psl); atomicAdd(&g_ad2[row],  pdl); }
            if (row2 < M) { atomicAdd(&g_as2[row2], psh); atomicAdd(&g_ad2[row2], pdh); }
        }
    }
}

// ---------------------------------------------------------------------------
// GAT1 fused: quarter-warp per edge (2 edges in flight), bf16 z, bf16 h2 out
// ---------------------------------------------------------------------------
__global__ void gat1_fused(const float* __restrict__ b1) {
    int gid = blockIdx.x * blockDim.x + threadIdx.x;
    int node = gid >> 5, lane = gid & 31;
    if (node >= N) return;
    int beg = g_off[node], deg = g_deg[node];
    const int q = lane >> 3, l8 = lane & 7;
    const float adh = g_ad1[(size_t)node * 8 + l8];

    float acc[8];
#pragma unroll
    for (int j = 0; j < 8; j++) acc[j] = 0.f;
    float den = 0.f;

    if (q == 0) {  // self-loop
        float w = __expf(lrelu(g_as1[(size_t)node * 8 + l8] + adh));
        uint4 u = *(const uint4*)&g_z1b[(size_t)node * 32 + l8 * 4];
        const uint32_t uu[4] = {u.x, u.y, u.z, u.w};
#pragma unroll
        for (int j = 0; j < 4; j++) {
            float2 p = unpack_bf16(uu[j]);
            acc[j*2] = w * p.x; acc[j*2+1] = w * p.y;
        }
        den = w;
    }
    int k = q;
    for (; k + 4 < deg; k += 8) {
        int s0 = g_csr[beg + k], s1 = g_csr[beg + k + 4];
        float w0 = __expf(lrelu(g_as1[(size_t)s0 * 8 + l8] + adh));
        float w1 = __expf(lrelu(g_as1[(size_t)s1 * 8 + l8] + adh));
        uint4 u0 = *(const uint4*)&g_z1b[(size_t)s0 * 32 + l8 * 4];
        uint4 u1 = *(const uint4*)&g_z1b[(size_t)s1 * 32 + l8 * 4];
        const uint32_t a0[4] = {u0.x, u0.y, u0.z, u0.w};
        const uint32_t a1[4] = {u1.x, u1.y, u1.z, u1.w};
#pragma unroll
        for (int j = 0; j < 4; j++) {
            float2 p0 = unpack_bf16(a0[j]), p1 = unpack_bf16(a1[j]);
            acc[j*2]   += w0 * p0.x + w1 * p1.x;
            acc[j*2+1] += w0 * p0.y + w1 * p1.y;
        }
        den += w0 + w1;
    }
    if (k < deg) {
        int s = g_csr[beg + k];
        float w = __expf(lrelu(g_as1[(size_t)s * 8 + l8] + adh));
        uint4 u = *(const uint4*)&g_z1b[(size_t)s * 32 + l8 * 4];
        const uint32_t uu[4] = {u.x, u.y, u.z, u.w};
#pragma unroll
        for (int j = 0; j < 4; j++) {
            float2 p = unpack_bf16(uu[j]);
            acc[j*2] += w * p.x; acc[j*2+1] += w * p.y;
        }
        den += w;
    }
#pragma unroll
    for (int j = 0; j < 8; j++) {
        acc[j] += __shfl_xor_sync(0xffffffff, acc[j], 8);
        acc[j] += __shfl_xor_sync(0xffffffff, acc[j], 16);
    }
    den += __shfl_xor_sync(0xffffffff, den, 8);
    den += __shfl_xor_sync(0xffffffff, den, 16);
    if (q == 0) {
        float rh = 1.f / (den + 1e-16f);
        const float* bb = b1 + l8 * 8;
        float4 b0 = *(const float4*)bb;
        float4 b4 = *(const float4*)(bb + 4);
        uint4 o;
        o.x = pack_bf16(elu1(acc[0] * rh + b0.x), elu1(acc[1] * rh + b0.y));
        o.y = pack_bf16(elu1(acc[2] * rh + b0.z), elu1(acc[3] * rh + b0.w));
        o.z = pack_bf16(elu1(acc[4] * rh + b4.x), elu1(acc[5] * rh + b4.y));
        o.w = pack_bf16(elu1(acc[6] * rh + b4.z), elu1(acc[7] * rh + b4.w));
        *(uint4*)&g_h2b[(size_t)node * 32 + l8 * 4] = o;
    }
}

// ---------------------------------------------------------------------------
// GAT2 fused + regression head; last block writes the final output
// ---------------------------------------------------------------------------
__global__ void gat2_fused(const float* __restrict__ Wr, const float* __restrict__ br,
                           const float* __restrict__ b2, float* __restrict__ out) {
    __shared__ float bp[8];
    int gid = blockIdx.x * blockDim.x + threadIdx.x;
    int node = gid >> 5, lane = gid & 31, wid = threadIdx.x >> 5;
    int beg = g_off[node], deg = g_deg[node];
    const int q = lane >> 3, l8 = lane & 7;
    const float adn = g_ad2[node];

    float acc[8];
#pragma unroll
    for (int j = 0; j < 8; j++) acc[j] = 0.f;
    float den = 0.f;

    if (q == 0) {
        float w = __expf(lrelu(g_as2[node] + adn));
        uint4 u = *(const uint4*)&g_z2b[(size_t)node * 32 + l8 * 4];
        const uint32_t uu[4] = {u.x, u.y, u.z, u.w};
#pragma unroll
        for (int j = 0; j < 4; j++) {
            float2 p = unpack_bf16(uu[j]);
            acc[j*2] = w * p.x; acc[j*2+1] = w * p.y;
        }
        den = w;
    }
    int k = q;
    for (; k + 4 < deg; k += 8) {
        int s0 = g_csr[beg + k], s1 = g_csr[beg + k + 4];
        float w0 = __expf(lrelu(g_as2[s0] + adn));
        float w1 = __expf(lrelu(g_as2[s1] + adn));
        uint4 u0 = *(const uint4*)&g_z2b[(size_t)s0 * 32 + l8 * 4];
        uint4 u1 = *(const uint4*)&g_z2b[(size_t)s1 * 32 + l8 * 4];
        const uint32_t a0[4] = {u0.x, u0.y, u0.z, u0.w};
        const uint32_t a1[4] = {u1.x, u1.y, u1.z, u1.w};
#pragma unroll
        for (int j = 0; j < 4; j++) {
            float2 p0 = unpack_bf16(a0[j]), p1 = unpack_bf16(a1[j]);
            acc[j*2]   += w0 * p0.x + w1 * p1.x;
            acc[j*2+1] += w0 * p0.y + w1 * p1.y;
        }
        den += w0 + w1;
    }
    if (k < deg) {
        int s = g_csr[beg + k];
        float w = __expf(lrelu(g_as2[s] + adn));
        uint4 u = *(const uint4*)&g_z2b[(size_t)s * 32 + l8 * 4];
        const uint32_t uu[4] = {u.x, u.y, u.z, u.w};
#pragma unroll
        for (int j = 0; j < 4; j++) {
            float2 p = unpack_bf16(uu[j]);
            acc[j*2] += w * p.x; acc[j*2+1] += w * p.y;
        }
        den += w;
    }
#pragma unroll
    for (int j = 0; j < 8; j++) {
        acc[j] += __shfl_xor_sync(0xffffffff, acc[j], 8);
        acc[j] += __shfl_xor_sync(0xffffffff, acc[j], 16);
    }
    den += __shfl_xor_sync(0xffffffff, den, 8);
    den += __shfl_xor_sync(0xffffffff, den, 16);

    float pd = 0.f;
    const float* wp = Wr + l8 * 8;
#pragma unroll
    for (int j = 0; j < 8; j++) pd += acc[j] * wp[j];
    pd += __shfl_xor_sync(0xffffffff, pd, 1);
    pd += __shfl_xor_sync(0xffffffff, pd, 2);
    pd += __shfl_xor_sync(0xffffffff, pd, 4);
    if (lane == 0) bp[wid] = pd / (den + 1e-16f);
    __syncthreads();
    if (threadIdx.x == 0) {
        float s = 0.f;
#pragma unroll
        for (int j = 0; j < 8; j++) s += bp[j];
        atomicAdd(&g_out_acc, s);
        __threadfence();
        unsigned old = atomicAdd(&g_done, 1u);
        if (old == gridDim.x - 1) {
            float total = atomicExch(&g_out_acc, 0.f);
            float bwr = 0.f;
            for (int i = 0; i < 64; i++) bwr += b2[i] * Wr[i];
            out[0] = total * (1.0f / (float)N) + bwr + br[0];
            g_done = 0;
        }
    }
}

// ---------------------------------------------------------------------------
// Launch
// ---------------------------------------------------------------------------
extern "C" void kernel_launch(void* const* d_in, const int* in_sizes, int n_in,
                              void* d_out, int out_size) {
    const float* x      = (const float*)d_in[0];
    const void*  ei     = d_in[1];
    const float* W_rel  = (const float*)d_in[2];
    const float* b_rel  = (const float*)d_in[3];
    const float* W_root = (const float*)d_in[4];
    const float* W1     = (const float*)d_in[5];
    const float* a1s    = (const float*)d_in[6];
    const float* a1d    = (const float*)d_in[7];
    const float* b1     = (const float*)d_in[8];
    const float* W2     = (const float*)d_in[9];
    const float* a2s    = (const float*)d_in[10];
    const float* a2d    = (const float*)d_in[11];
    const float* b2     = (const float*)d_in[12];
    const float* Wr     = (const float*)d_in[13];
    const float* br     = (const float*)d_in[14];
    float* out          = (float*)d_out;

    uint32_t *p_xb, *p_nbrb, *p_z1b, *p_h2b, *p_z2b;
    cudaGetSymbolAddress((void**)&p_xb,   g_xb);
    cudaGetSymbolAddress((void**)&p_nbrb, g_nbrb);
    cudaGetSymbolAddress((void**)&p_z1b,  g_z1b);
    cudaGetSymbolAddress((void**)&p_h2b,  g_h2b);
    cudaGetSymbolAddress((void**)&p_z2b,  g_z2b);

    init_kernel<<<256, 256>>>((const int*)ei);

    hist_kernel<<<(E + 255) / 256, 256>>>(ei);
    scan_conv_kernel<<<1 + CONV_B, 1024>>>(x);
    fill_kernel<<<(E / 2 + 255) / 256, 256>>>();

    gather_nbr_kernel<<<(N * 32 + 255) / 256, 256>>>();

    // fused GraphConv GEMM + GAT1 projection GEMM
    fused_gemm01<<<(N + 127) / 128, 256>>>(p_nbrb, W_rel, p_xb, W_root,
                                           b_rel, W1, p_z1b, a1s, a1d, N);
    gat1_fused<<<(N * 32 + 255) / 256, 256>>>(b1);

    {
        dim3 g((N + 127) / 128, 1);
        bf16_linear2<64><<<g, 256>>>(p_h2b, W2, 64, p_z2b, a2s, a2d, N, 64);
    }
    gat2_fused<<<N * 32 / 256, 256>>>(Wr, br, b2, out);
}

// round 17
// speedup vs baseline: 1.3142x; 1.0679x over previous
#include <cuda_runtime.h>
#include <cuda_bf16.h>
#include <math.h>
#include <stdint.h>

constexpr int N = 50000;
constexpr int E = 800000;

// ---------------------------------------------------------------------------
// Device scratch
// ---------------------------------------------------------------------------
__device__ __align__(16) uint32_t g_xb  [N * 64];  // x as bf16x2 (128 ch)
__device__ __align__(16) uint32_t g_nbrb[N * 64];  // nbr sums as bf16x2
__device__ __align__(16) uint32_t g_z1b [N * 32];  // z1 as bf16x2 (64 ch)
__device__ __align__(16) uint32_t g_h2b [N * 32];  // h2 as bf16x2
__device__ __align__(16) float g_as1[N * 8];
__device__ __align__(16) float g_ad1[N * 8];
__device__ float g_as2[N];
__device__ float g_ad2[N];
__device__ float g_y2 [N];           // z2 . Wr per node
__device__ float g_out_acc;          // reset by gat2 last block
__device__ unsigned g_done;          // reset by gat2 last block
__device__ int g_deg[N];
__device__ int g_off[N];
__device__ unsigned long long g_pack[E];
__device__ int g_csr[E];
__device__ int g_is64;

// ---------------------------------------------------------------------------
// Helpers
// ---------------------------------------------------------------------------
__device__ __forceinline__ float lrelu(float x) { return x > 0.f ? x : 0.2f * x; }
__device__ __forceinline__ float elu1(float x)  { return x > 0.f ? x : __expf(x) - 1.f; }

__device__ __forceinline__ uint32_t pack_bf16(float a, float b) {
    __nv_bfloat162 v = __float22bfloat162_rn(make_float2(a, b));
    return *reinterpret_cast<uint32_t*>(&v);
}
__device__ __forceinline__ float2 unpack_bf16(uint32_t u) {
    return __bfloat1622float2(*reinterpret_cast<__nv_bfloat162*>(&u));
}

// m16n8k16 bf16 MMA, fp32 accumulate
__device__ __forceinline__ void mma_bf16(float c[4], const uint4& a, const uint2& b) {
    asm volatile(
        "mma.sync.aligned.m16n8k16.row.col.f32.bf16.bf16.f32 "
        "{%0,%1,%2,%3}, {%4,%5,%6,%7}, {%8,%9}, {%0,%1,%2,%3};"
        : "+f"(c[0]), "+f"(c[1]), "+f"(c[2]), "+f"(c[3])
        : "r"(a.x), "r"(a.y), "r"(a.z), "r"(a.w), "r"(b.x), "r"(b.y));
}

__device__ __forceinline__ int edge_id(const void* ei, long long idx) {
    return g_is64 ? (int)((const long long*)ei)[idx] : ((const int*)ei)[idx];
}
__device__ __forceinline__ int edge_src(const void* ei, int e) { return edge_id(ei, e); }
__device__ __forceinline__ int edge_dst(const void* ei, int e) { return edge_id(ei, (long long)E + e); }

// ---------------------------------------------------------------------------
// init: zero counters + dtype detect (block 0)
// ---------------------------------------------------------------------------
__global__ void init_kernel(const int* ei) {
    int i = blockIdx.x * blockDim.x + threadIdx.x;
    int stride = gridDim.x * blockDim.x;
    for (int t = i; t < N; t += stride) {
        g_deg[t] = 0; g_as2[t] = 0.f; g_ad2[t] = 0.f; g_y2[t] = 0.f;
    }
    if (blockIdx.x == 0) {
        __shared__ int any;
        if (threadIdx.x == 0) any = 0;
        __syncthreads();
        for (int t = threadIdx.x; t < 1024; t += blockDim.x)
            if (ei[2 * t + 1] != 0) atomicOr(&any, 1);
        __syncthreads();
        if (threadIdx.x == 0) g_is64 = any ? 0 : 1;
    }
}

// ---------------------------------------------------------------------------
// hist: rank capture + packed (src|dst|rank) payload (2 edges/thread)
// ---------------------------------------------------------------------------
__global__ void hist_kernel(const void* __restrict__ ei) {
    int e = (blockIdx.x * blockDim.x + threadIdx.x) * 2;
    if (e >= E) return;
    int s0 = edge_src(ei, e),     d0 = edge_dst(ei, e);
    int s1 = edge_src(ei, e + 1), d1 = edge_dst(ei, e + 1);
    unsigned r0 = atomicAdd(&g_deg[d0], 1);
    unsigned r1 = atomicAdd(&g_deg[d1], 1);
    g_pack[e] = (unsigned long long)(unsigned)s0
              | ((unsigned long long)(unsigned)d0 << 16)
              | ((unsigned long long)r0 << 32);
    g_pack[e + 1] = (unsigned long long)(unsigned)s1
                  | ((unsigned long long)(unsigned)d1 << 16)
                  | ((unsigned long long)r1 << 32);
}

// ---------------------------------------------------------------------------
// scan (block 0) + x->bf16 convert (blocks >= 1, riding in the scan's shadow)
// ---------------------------------------------------------------------------
constexpr int CONV_B = (N * 64 / 8 + 1023) / 1024;   // 391 blocks of 1024 thr

__global__ void scan_conv_kernel(const float* __restrict__ x) {
    if (blockIdx.x > 0) {
        int idx = (((int)blockIdx.x - 1) * 1024 + threadIdx.x) * 8;
        if (idx >= N * 64) return;
        const float4* xin = (const float4*)(x + (size_t)idx * 2);
        float4 v0 = xin[0], v1 = xin[1], v2 = xin[2], v3 = xin[3];
        uint4 o0, o1;
        o0.x = pack_bf16(v0.x, v0.y); o0.y = pack_bf16(v0.z, v0.w);
        o0.z = pack_bf16(v1.x, v1.y); o0.w = pack_bf16(v1.z, v1.w);
        o1.x = pack_bf16(v2.x, v2.y); o1.y = pack_bf16(v2.z, v2.w);
        o1.z = pack_bf16(v3.x, v3.y); o1.w = pack_bf16(v3.z, v3.w);
        *(uint4*)&g_xb[idx]     = o0;
        *(uint4*)&g_xb[idx + 4] = o1;
        return;
    }
    __shared__ int wsum[32];
    __shared__ int s_carry;
    int tid = threadIdx.x, lane = tid & 31, wid = tid >> 5;
    if (tid == 0) s_carry = 0;
    __syncthreads();
    for (int base = 0; base < N; base += 1024) {
        int i = base + tid;
        int v = (i < N) ? g_deg[i] : 0;
        int s = v;
#pragma unroll
        for (int o = 1; o < 32; o <<= 1) {
            int u = __shfl_up_sync(0xffffffff, s, o);
            if (lane >= o) s += u;
        }
        if (lane == 31) wsum[wid] = s;
        __syncthreads();
        if (wid == 0) {
            int w = wsum[lane];
#pragma unroll
            for (int o = 1; o < 32; o <<= 1) {
                int u = __shfl_up_sync(0xffffffff, w, o);
                if (lane >= o) w += u;
            }
            wsum[lane] = w;
        }
        __syncthreads();
        int prev = (wid > 0) ? wsum[wid - 1] : 0;
        int carry = s_carry;
        if (i < N) g_off[i] = carry + prev + s - v;
        __syncthreads();
        if (tid == 1023) s_carry = carry + wsum[31];
        __syncthreads();
    }
}

// fill: 2 edges per thread, one 16B pack load
__global__ void fill_kernel() {
    int e = (blockIdx.x * blockDim.x + threadIdx.x) * 2;
    if (e >= E) return;
    ulonglong2 pp = *(const ulonglong2*)&g_pack[e];
    {
        unsigned long long p = pp.x;
        g_csr[g_off[(int)((p >> 16) & 0xffffu)] + (int)(p >> 32)] = (int)(p & 0xffffu);
    }
    {
        unsigned long long p = pp.y;
        g_csr[g_off[(int)((p >> 16) & 0xffffu)] + (int)(p >> 32)] = (int)(p & 0xffffu);
    }
}

// ---------------------------------------------------------------------------
// GraphConv gather: quarter-warp per edge, bf16 x, fp32 accum, bf16 out
// ---------------------------------------------------------------------------
__global__ __launch_bounds__(256, 6) void gather_nbr_kernel() {
    int gid = blockIdx.x * blockDim.x + threadIdx.x;
    int node = gid >> 5, lane = gid & 31;
    if (node >= N) return;
    int beg = g_off[node], deg = g_deg[node];
    const int q = lane >> 3, l8 = lane & 7;

    float acc[16];
#pragma unroll
    for (int j = 0; j < 16; j++) acc[j] = 0.f;

    int k = q;
    for (; k + 4 < deg; k += 8) {
        int s0 = g_csr[beg + k], s1 = g_csr[beg + k + 4];
        uint4 a0 = *(const uint4*)&g_xb[(size_t)s0 * 64 + l8 * 8];
        uint4 b0 = *(const uint4*)&g_xb[(size_t)s0 * 64 + l8 * 8 + 4];
        uint4 a1 = *(const uint4*)&g_xb[(size_t)s1 * 64 + l8 * 8];
        uint4 b1 = *(const uint4*)&g_xb[(size_t)s1 * 64 + l8 * 8 + 4];
        const uint32_t u0[8] = {a0.x,a0.y,a0.z,a0.w,b0.x,b0.y,b0.z,b0.w};
        const uint32_t u1[8] = {a1.x,a1.y,a1.z,a1.w,b1.x,b1.y,b1.z,b1.w};
#pragma unroll
        for (int j = 0; j < 8; j++) {
            float2 p0 = unpack_bf16(u0[j]), p1 = unpack_bf16(u1[j]);
            acc[j*2]   += p0.x + p1.x;
            acc[j*2+1] += p0.y + p1.y;
        }
    }
    if (k < deg) {
        int s = g_csr[beg + k];
        uint4 a = *(const uint4*)&g_xb[(size_t)s * 64 + l8 * 8];
        uint4 b = *(const uint4*)&g_xb[(size_t)s * 64 + l8 * 8 + 4];
        const uint32_t u[8] = {a.x,a.y,a.z,a.w,b.x,b.y,b.z,b.w};
#pragma unroll
        for (int j = 0; j < 8; j++) {
            float2 p = unpack_bf16(u[j]);
            acc[j*2] += p.x; acc[j*2+1] += p.y;
        }
    }
#pragma unroll
    for (int j = 0; j < 16; j++) {
        acc[j] += __shfl_xor_sync(0xffffffff, acc[j], 8);
        acc[j] += __shfl_xor_sync(0xffffffff, acc[j], 16);
    }
    if (q == 0) {
        uint32_t* dst = g_nbrb + (size_t)node * 64 + l8 * 8;
        uint4 o0, o1;
        o0.x = pack_bf16(acc[0],  acc[1]);  o0.y = pack_bf16(acc[2],  acc[3]);
        o0.z = pack_bf16(acc[4],  acc[5]);  o0.w = pack_bf16(acc[6],  acc[7]);
        o1.x = pack_bf16(acc[8],  acc[9]);  o1.y = pack_bf16(acc[10], acc[11]);
        o1.z = pack_bf16(acc[12], acc[13]); o1.w = pack_bf16(acc[14], acc[15]);
        *(uint4*)dst       = o0;
        *(uint4*)(dst + 4) = o1;
    }
}

// ---------------------------------------------------------------------------
// FUSED gemm0+gemm1 (unchanged from round 16)
// ---------------------------------------------------------------------------
__global__ __launch_bounds__(256) void fused_gemm01(
    const uint32_t* __restrict__ A1b, const float* __restrict__ Wa,
    const uint32_t* __restrict__ A2b, const float* __restrict__ Wb,
    const float* __restrict__ bias, const float* __restrict__ W1,
    uint32_t* __restrict__ Zb, const float* __restrict__ aS,
    const float* __restrict__ aD, int M)
{
    __shared__ __align__(16) uint32_t As[2][8][128];
    __shared__ __align__(16) uint32_t Bs[2][16][64];
    __shared__ __align__(16) uint32_t Hs[8][8][128];
    const int tid  = threadIdx.x;
    const int lane = tid & 31, warp = tid >> 5;
    const int wm = warp & 3, wn = warp >> 2;
    const int row0 = blockIdx.x * 128;
    const int r = lane >> 2, cc = (lane & 3) * 2;

    {
        float acc1[2][8][4];
#pragma unroll
        for (int mt = 0; mt < 2; mt++)
#pragma unroll
            for (int nt = 0; nt < 8; nt++)
#pragma unroll
                for (int j = 0; j < 4; j++) acc1[mt][nt][j] = 0.f;

        for (int t = 0; t < 8; t++) {
            const uint32_t* Ab = (t < 4) ? A1b : A2b;
            const float* W     = (t < 4) ? Wa  : Wb;
            int kb = (t & 3) << 5;
            __syncthreads();
#pragma unroll
            for (int i = 0; i < 4; i++) {
                int idx = tid + i * 256;
                int m = idx >> 3, k4 = (idx & 7) << 2;
                uint2 u = make_uint2(0u, 0u);
                if (row0 + m < M)
                    u = *(const uint2*)(Ab + (size_t)(row0 + m) * 64 + ((kb + k4) >> 1));
                int m16 = m >> 4, mm = m & 15, rr = mm >> 3, rq = mm & 7;
                int slab = k4 >> 4, kk = k4 & 15;
                int c0l = (kk >> 1) & 3;
                int reg = rr + 2 * ((kk >> 3) & 1);
                As[slab][m16][(rq * 4 + c0l) * 4 + reg]     = u.x;
                As[slab][m16][(rq * 4 + c0l + 1) * 4 + reg] = u.y;
            }
#pragma unroll
            for (int i = 0; i < 4; i++) {
                int idx = tid + i * 256;
                int n = idx >> 3, k4 = (idx & 7) << 2;
                float4 v = *(const float4*)(W + (size_t)n * 128 + kb + k4);
                uint32_t p0 = pack_bf16(v.x, v.y), p1 = pack_bf16(v.z, v.w);
                int n8 = n >> 3, nn = n & 7;
                int slab = k4 >> 4, kk = k4 & 15;
                int c0l = (kk >> 1) & 3;
                int reg = (kk >> 3) & 1;
                Bs[slab][n8][(nn * 4 + c0l) * 2 + reg]     = p0;
                Bs[slab][n8][(nn * 4 + c0l + 1) * 2 + reg] = p1;
            }
            __syncthreads();
#pragma unroll
            for (int k16 = 0; k16 < 2; k16++) {
                uint4 a[2];
                uint2 b[8];
                a[0] = *(const uint4*)&As[k16][wm * 2 + 0][lane * 4];
                a[1] = *(const uint4*)&As[k16][wm * 2 + 1][lane * 4];
#pragma unroll
                for (int nt = 0; nt < 8; nt++)
                    b[nt] = *(const uint2*)&Bs[k16][wn * 8 + nt][lane * 2];
#pragma unroll
                for (int mt = 0; mt < 2; mt++)
#pragma unroll
                    for (int nt = 0; nt < 8; nt++)
                        mma_bf16(acc1[mt][nt], a[mt], b[nt]);
            }
        }

        __syncthreads();
#pragma unroll
        for (int mt = 0; mt < 2; mt++) {
            int m16 = wm * 2 + mt;
#pragma unroll
            for (int nt = 0; nt < 8; nt++) {
                int col = (wn * 8 + nt) * 8 + cc;
                float bx = bias[col], by = bias[col + 1];
                uint32_t plo = pack_bf16(elu1(acc1[mt][nt][0] + bx), elu1(acc1[mt][nt][1] + by));
                uint32_t phi = pack_bf16(elu1(acc1[mt][nt][2] + bx), elu1(acc1[mt][nt][3] + by));
                int slab = col >> 4, kk = col & 15;
                int c0l = (kk >> 1) & 3;
                int kreg = 2 * ((kk >> 3) & 1);
                Hs[slab][m16][(r * 4 + c0l) * 4 + kreg]     = plo;
                Hs[slab][m16][(r * 4 + c0l) * 4 + kreg + 1] = phi;
            }
        }
    }
    __syncthreads();

    float acc2[2][4][4];
#pragma unroll
    for (int mt = 0; mt < 2; mt++)
#pragma unroll
        for (int nt = 0; nt < 4; nt++)
#pragma unroll
            for (int j = 0; j < 4; j++) acc2[mt][nt][j] = 0.f;

    for (int t2 = 0; t2 < 4; t2++) {
        int kb = t2 << 5;
        __syncthreads();
#pragma unroll
        for (int i = 0; i < 2; i++) {
            int idx = tid + i * 256;
            int n = idx >> 3, k4 = (idx & 7) << 2;
            float4 v = *(const float4*)(W1 + (size_t)n * 128 + kb + k4);
            uint32_t p0 = pack_bf16(v.x, v.y), p1 = pack_bf16(v.z, v.w);
            int n8 = n >> 3, nn = n & 7;
            int slab = k4 >> 4, kk = k4 & 15;
            int c0l = (kk >> 1) & 3;
            int reg = (kk >> 3) & 1;
            Bs[slab][n8][(nn * 4 + c0l) * 2 + reg]     = p0;
            Bs[slab][n8][(nn * 4 + c0l + 1) * 2 + reg] = p1;
        }
        __syncthreads();
#pragma unroll
        for (int k16 = 0; k16 < 2; k16++) {
            int gs = t2 * 2 + k16;
            uint4 a[2];
            uint2 b[4];
            a[0] = *(const uint4*)&Hs[gs][wm * 2 + 0][lane * 4];
            a[1] = *(const uint4*)&Hs[gs][wm * 2 + 1][lane * 4];
#pragma unroll
            for (int nt = 0; nt < 4; nt++)
                b[nt] = *(const uint2*)&Bs[k16][wn * 4 + nt][lane * 2];
#pragma unroll
            for (int mt = 0; mt < 2; mt++)
#pragma unroll
                for (int nt = 0; nt < 4; nt++)
                    mma_bf16(acc2[mt][nt], a[mt], b[nt]);
        }
    }

#pragma unroll
    for (int mt = 0; mt < 2; mt++) {
        int row  = row0 + (wm * 2 + mt) * 16 + r;
        int row2 = row + 8;
#pragma unroll
        for (int nt = 0; nt < 4; nt++) {
            int col = (wn * 4 + nt) * 8 + cc;
            float v0 = acc2[mt][nt][0], v1 = acc2[mt][nt][1];
            float v2 = acc2[mt][nt][2], v3 = acc2[mt][nt][3];
            if (row  < M) Zb[(size_t)row  * 32 + (col >> 1)] = pack_bf16(v0, v1);
            if (row2 < M) Zb[(size_t)row2 * 32 + (col >> 1)] = pack_bf16(v2, v3);
            float s0 = aS[col], s1 = aS[col + 1];
            float d0 = aD[col], d1 = aD[col + 1];
            int h = wn * 4 + nt;
            float ps_lo = v0 * s0 + v1 * s1;
            float pd_lo = v0 * d0 + v1 * d1;
            float ps_hi = v2 * s0 + v3 * s1;
            float pd_hi = v2 * d0 + v3 * d1;
            ps_lo += __shfl_xor_sync(0xffffffff, ps_lo, 1);
            ps_lo += __shfl_xor_sync(0xffffffff, ps_lo, 2);
            pd_lo += __shfl_xor_sync(0xffffffff, pd_lo, 1);
            pd_lo += __shfl_xor_sync(0xffffffff, pd_lo, 2);
            ps_hi += __shfl_xor_sync(0xffffffff, ps_hi, 1);
            ps_hi += __shfl_xor_sync(0xffffffff, ps_hi, 2);
            pd_hi += __shfl_xor_sync(0xffffffff, pd_hi, 1);
            pd_hi += __shfl_xor_sync(0xffffffff, pd_hi, 2);
            if ((lane & 3) == 0) {
                if (row  < M) { g_as1[(size_t)row  * 8 + h] = ps_lo; g_ad1[(size_t)row  * 8 + h] = pd_lo; }
                if (row2 < M) { g_as1[(size_t)row2 * 8 + h] = ps_hi; g_ad1[(size_t)row2 * 8 + h] = pd_hi; }
            }
        }
    }
}

// ---------------------------------------------------------------------------
// gemm2: z2 = h2@W2^T -> only scalars as2, ad2, y (= z2.Wr). No z2 store.
// ---------------------------------------------------------------------------
__global__ __launch_bounds__(256) void bf16_linear2(
    const uint32_t* __restrict__ A1b, const float* __restrict__ Wa,
    const float* __restrict__ aS, const float* __restrict__ aD,
    const float* __restrict__ Wr, int M)
{
    constexpr int K1 = 64, NT = 4;
    __shared__ __align__(16) uint32_t As[2][8][128];
    __shared__ __align__(16) uint32_t Bs[2][8][64];
    const int tid  = threadIdx.x;
    const int lane = tid & 31, warp = tid >> 5;
    const int wm = warp & 3, wn = warp >> 2;
    const int row0 = blockIdx.x * 128;

    float acc[2][NT][4];
#pragma unroll
    for (int mt = 0; mt < 2; mt++)
#pragma unroll
        for (int nt = 0; nt < NT; nt++)
#pragma unroll
            for (int j = 0; j < 4; j++) acc[mt][nt][j] = 0.f;

    for (int t = 0; t < 2; t++) {
        int kb = t << 5;
        __syncthreads();
#pragma unroll
        for (int i = 0; i < 4; i++) {
            int idx = tid + i * 256;
            int m = idx >> 3, k4 = (idx & 7) << 2;
            uint2 u = make_uint2(0u, 0u);
            if (row0 + m < M)
                u = *(const uint2*)(A1b + (size_t)(row0 + m) * 32 + ((kb + k4) >> 1));
            int m16 = m >> 4, mm = m & 15, rr = mm >> 3, rq = mm & 7;
            int slab = k4 >> 4, kk = k4 & 15;
            int c0l = (kk >> 1) & 3;
            int reg = rr + 2 * ((kk >> 3) & 1);
            As[slab][m16][(rq * 4 + c0l) * 4 + reg]     = u.x;
            As[slab][m16][(rq * 4 + c0l + 1) * 4 + reg] = u.y;
        }
#pragma unroll
        for (int i = 0; i < 2; i++) {
            int idx = tid + i * 256;
            int n = idx >> 3, k4 = (idx & 7) << 2;
            float4 v = *(const float4*)(Wa + (size_t)n * K1 + kb + k4);
            uint32_t p0 = pack_bf16(v.x, v.y), p1 = pack_bf16(v.z, v.w);
            int n8 = n >> 3, nn = n & 7;
            int slab = k4 >> 4, kk = k4 & 15;
            int c0l = (kk >> 1) & 3;
            int reg = (kk >> 3) & 1;
            Bs[slab][n8][(nn * 4 + c0l) * 2 + reg]     = p0;
            Bs[slab][n8][(nn * 4 + c0l + 1) * 2 + reg] = p1;
        }
        __syncthreads();
#pragma unroll
        for (int k16 = 0; k16 < 2; k16++) {
            uint4 a[2];
            uint2 b[NT];
            a[0] = *(const uint4*)&As[k16][wm * 2 + 0][lane * 4];
            a[1] = *(const uint4*)&As[k16][wm * 2 + 1][lane * 4];
#pragma unroll
            for (int nt = 0; nt < NT; nt++)
                b[nt] = *(const uint2*)&Bs[k16][wn * NT + nt][lane * 2];
#pragma unroll
            for (int mt = 0; mt < 2; mt++)
#pragma unroll
                for (int nt = 0; nt < NT; nt++)
                    mma_bf16(acc[mt][nt], a[mt], b[nt]);
        }
    }

    const int r = lane >> 2, cc = (lane & 3) * 2;
#pragma unroll
    for (int mt = 0; mt < 2; mt++) {
        int row  = row0 + (wm * 2 + mt) * 16 + r;
        int row2 = row + 8;
        float psl = 0.f, pdl = 0.f, pyl = 0.f;
        float psh = 0.f, pdh = 0.f, pyh = 0.f;
#pragma unroll
        for (int nt = 0; nt < NT; nt++) {
            int col = (wn * NT + nt) * 8 + cc;
            float v0 = acc[mt][nt][0], v1 = acc[mt][nt][1];
            float v2 = acc[mt][nt][2], v3 = acc[mt][nt][3];
            float s0 = aS[col], s1 = aS[col + 1];
            float d0 = aD[col], d1 = aD[col + 1];
            float w0 = Wr[col], w1 = Wr[col + 1];
            psl += v0 * s0 + v1 * s1;
            pdl += v0 * d0 + v1 * d1;
            pyl += v0 * w0 + v1 * w1;
            psh += v2 * s0 + v3 * s1;
            pdh += v2 * d0 + v3 * d1;
            pyh += v2 * w0 + v3 * w1;
        }
        psl += __shfl_xor_sync(0xffffffff, psl, 1);
        psl += __shfl_xor_sync(0xffffffff, psl, 2);
        pdl += __shfl_xor_sync(0xffffffff, pdl, 1);
        pdl += __shfl_xor_sync(0xffffffff, pdl, 2);
        pyl += __shfl_xor_sync(0xffffffff, pyl, 1);
        pyl += __shfl_xor_sync(0xffffffff, pyl, 2);
        psh += __shfl_xor_sync(0xffffffff, psh, 1);
        psh += __shfl_xor_sync(0xffffffff, psh, 2);
        pdh += __shfl_xor_sync(0xffffffff, pdh, 1);
        pdh += __shfl_xor_sync(0xffffffff, pdh, 2);
        pyh += __shfl_xor_sync(0xffffffff, pyh, 1);
        pyh += __shfl_xor_sync(0xffffffff, pyh, 2);
        if ((lane & 3) == 0) {
            if (row < M) {
                atomicAdd(&g_as2[row], psl);
                atomicAdd(&g_ad2[row], pdl);
                atomicAdd(&g_y2[row],  pyl);
            }
            if (row2 < M) {
                atomicAdd(&g_as2[row2], psh);
                atomicAdd(&g_ad2[row2], pdh);
                atomicAdd(&g_y2[row2],  pyh);
            }
        }
    }
}

// ---------------------------------------------------------------------------
// GAT1 fused: quarter-warp per edge (2 edges in flight), bf16 z, bf16 h2 out
// ---------------------------------------------------------------------------
__global__ void gat1_fused(const float* __restrict__ b1) {
    int gid = blockIdx.x * blockDim.x + threadIdx.x;
    int node = gid >> 5, lane = gid & 31;
    if (node >= N) return;
    int beg = g_off[node], deg = g_deg[node];
    const int q = lane >> 3, l8 = lane & 7;
    const float adh = g_ad1[(size_t)node * 8 + l8];

    float acc[8];
#pragma unroll
    for (int j = 0; j < 8; j++) acc[j] = 0.f;
    float den = 0.f;

    if (q == 0) {  // self-loop
        float w = __expf(lrelu(g_as1[(size_t)node * 8 + l8] + adh));
        uint4 u = *(const uint4*)&g_z1b[(size_t)node * 32 + l8 * 4];
        const uint32_t uu[4] = {u.x, u.y, u.z, u.w};
#pragma unroll
        for (int j = 0; j < 4; j++) {
            float2 p = unpack_bf16(uu[j]);
            acc[j*2] = w * p.x; acc[j*2+1] = w * p.y;
        }
        den = w;
    }
    int k = q;
    for (; k + 4 < deg; k += 8) {
        int s0 = g_csr[beg + k], s1 = g_csr[beg + k + 4];
        float w0 = __expf(lrelu(g_as1[(size_t)s0 * 8 + l8] + adh));
        float w1 = __expf(lrelu(g_as1[(size_t)s1 * 8 + l8] + adh));
        uint4 u0 = *(const uint4*)&g_z1b[(size_t)s0 * 32 + l8 * 4];
        uint4 u1 = *(const uint4*)&g_z1b[(size_t)s1 * 32 + l8 * 4];
        const uint32_t a0[4] = {u0.x, u0.y, u0.z, u0.w};
        const uint32_t a1[4] = {u1.x, u1.y, u1.z, u1.w};
#pragma unroll
        for (int j = 0; j < 4; j++) {
            float2 p0 = unpack_bf16(a0[j]), p1 = unpack_bf16(a1[j]);
            acc[j*2]   += w0 * p0.x + w1 * p1.x;
            acc[j*2+1] += w0 * p0.y + w1 * p1.y;
        }
        den += w0 + w1;
    }
    if (k < deg) {
        int s = g_csr[beg + k];
        float w = __expf(lrelu(g_as1[(size_t)s * 8 + l8] + adh));
        uint4 u = *(const uint4*)&g_z1b[(size_t)s * 32 + l8 * 4];
        const uint32_t uu[4] = {u.x, u.y, u.z, u.w};
#pragma unroll
        for (int j = 0; j < 4; j++) {
            float2 p = unpack_bf16(uu[j]);
            acc[j*2] += w * p.x; acc[j*2+1] += w * p.y;
        }
        den += w;
    }
#pragma unroll
    for (int j = 0; j < 8; j++) {
        acc[j] += __shfl_xor_sync(0xffffffff, acc[j], 8);
        acc[j] += __shfl_xor_sync(0xffffffff, acc[j], 16);
    }
    den += __shfl_xor_sync(0xffffffff, den, 8);
    den += __shfl_xor_sync(0xffffffff, den, 16);
    if (q == 0) {
        float rh = 1.f / (den + 1e-16f);
        const float* bb = b1 + l8 * 8;
        float4 b0 = *(const float4*)bb;
        float4 b4 = *(const float4*)(bb + 4);
        uint4 o;
        o.x = pack_bf16(elu1(acc[0] * rh + b0.x), elu1(acc[1] * rh + b0.y));
        o.y = pack_bf16(elu1(acc[2] * rh + b0.z), elu1(acc[3] * rh + b0.w));
        o.z = pack_bf16(elu1(acc[4] * rh + b4.x), elu1(acc[5] * rh + b4.y));
        o.w = pack_bf16(elu1(acc[6] * rh + b4.z), elu1(acc[7] * rh + b4.w));
        *(uint4*)&g_h2b[(size_t)node * 32 + l8 * 4] = o;
    }
}

// ---------------------------------------------------------------------------
// GAT2 scalar: per node num = sum w*y_s, den = sum w; out accumulation
// ---------------------------------------------------------------------------
__global__ void gat2_fused(const float* __restrict__ Wr, const float* __restrict__ br,
                           const float* __restrict__ b2, float* __restrict__ out) {
    __shared__ float bp[8];
    int gid = blockIdx.x * blockDim.x + threadIdx.x;
    int node = gid >> 5, lane = gid & 31, wid = threadIdx.x >> 5;
    int beg = g_off[node], deg = g_deg[node];
    const float adn = g_ad2[node];

    float num = 0.f, den = 0.f;
    if (lane == 0) {  // self-loop
        float w = __expf(lrelu(g_as2[node] + adn));
        num = w * g_y2[node];
        den = w;
    }
    for (int k = lane; k < deg; k += 32) {
        int s = g_csr[beg + k];
        float w = __expf(lrelu(g_as2[s] + adn));
        num += w * g_y2[s];
        den += w;
    }
#pragma unroll
    for (int o = 16; o; o >>= 1) {
        num += __shfl_xor_sync(0xffffffff, num, o);
        den += __shfl_xor_sync(0xffffffff, den, o);
    }
    if (lane == 0) bp[wid] = num / (den + 1e-16f);
    __syncthreads();
    if (threadIdx.x == 0) {
        float s = 0.f;
#pragma unroll
        for (int j = 0; j < 8; j++) s += bp[j];
        atomicAdd(&g_out_acc, s);
        __threadfence();
        unsigned old = atomicAdd(&g_done, 1u);
        if (old == gridDim.x - 1) {
            float total = atomicExch(&g_out_acc, 0.f);
            float bwr = 0.f;
            for (int i = 0; i < 64; i++) bwr += b2[i] * Wr[i];
            out[0] = total * (1.0f / (float)N) + bwr + br[0];
            g_done = 0;
        }
    }
}

// ---------------------------------------------------------------------------
// Launch
// ---------------------------------------------------------------------------
extern "C" void kernel_launch(void* const* d_in, const int* in_sizes, int n_in,
                              void* d_out, int out_size) {
    const float* x      = (const float*)d_in[0];
    const void*  ei     = d_in[1];
    const float* W_rel  = (const float*)d_in[2];
    const float* b_rel  = (const float*)d_in[3];
    const float* W_root = (const float*)d_in[4];
    const float* W1     = (const float*)d_in[5];
    const float* a1s    = (const float*)d_in[6];
    const float* a1d    = (const float*)d_in[7];
    const float* b1     = (const float*)d_in[8];
    const float* W2     = (const float*)d_in[9];
    const float* a2s    = (const float*)d_in[10];
    const float* a2d    = (const float*)d_in[11];
    const float* b2     = (const float*)d_in[12];
    const float* Wr     = (const float*)d_in[13];
    const float* br     = (const float*)d_in[14];
    float* out          = (float*)d_out;

    uint32_t *p_xb, *p_nbrb, *p_z1b, *p_h2b;
    cudaGetSymbolAddress((void**)&p_xb,   g_xb);
    cudaGetSymbolAddress((void**)&p_nbrb, g_nbrb);
    cudaGetSymbolAddress((void**)&p_z1b,  g_z1b);
    cudaGetSymbolAddress((void**)&p_h2b,  g_h2b);

    init_kernel<<<256, 256>>>((const int*)ei);

    hist_kernel<<<(E / 2 + 255) / 256, 256>>>(ei);
    scan_conv_kernel<<<1 + CONV_B, 1024>>>(x);
    fill_kernel<<<(E / 2 + 255) / 256, 256>>>();

    gather_nbr_kernel<<<(N * 32 + 255) / 256, 256>>>();

    fused_gemm01<<<(N + 127) / 128, 256>>>(p_nbrb, W_rel, p_xb, W_root,
                                           b_rel, W1, p_z1b, a1s, a1d, N);
    gat1_fused<<<(N * 32 + 255) / 256, 256>>>(b1);

    bf16_linear2<<<(N + 127) / 128, 256>>>(p_h2b, W2, a2s, a2d, Wr, N);
    gat2_fused<<<N * 32 / 256, 256>>>(Wr, br, b2, out);
}